// round 4
// baseline (speedup 1.0000x reference)
#include <cuda_runtime.h>

#define NN 50000
#define NE 800000
#define NG 512

// ---------------- device scratch (static, no runtime alloc) ----------------
__device__ float g_h0[NN * 128];
__device__ float g_h1[NN * 128];
__device__ float g_P [NN * 512];     // node projections [fd|sd|fs|ss]; reused as MLP temporaries
__device__ float g_Wcat[512 * 128];
__device__ float g_bcat[512];
__device__ float g_pool[NG * 128];
__device__ float g_t0g[NG * 256];
__device__ float g_t1g[NG * 256];
__device__ float g_gfin[NG * 128];

// ---------------- f32x2 helpers ----------------
typedef unsigned long long u64;
__device__ __forceinline__ u64 pk2(float lo, float hi) {
    u64 r; asm("mov.b64 %0,{%1,%2};" : "=l"(r) : "f"(lo), "f"(hi)); return r;
}
__device__ __forceinline__ float2 up2(u64 v) {
    float2 r; asm("mov.b64 {%0,%1},%2;" : "=f"(r.x), "=f"(r.y) : "l"(v)); return r;
}
__device__ __forceinline__ u64 ffma2(u64 a, u64 b, u64 c) {
    u64 d; asm("fma.rn.f32x2 %0,%1,%2,%3;" : "=l"(d) : "l"(a), "l"(b), "l"(c)); return d;
}
__device__ __forceinline__ u64 fadd2(u64 a, u64 b) {
    u64 d; asm("add.rn.f32x2 %0,%1,%2;" : "=l"(d) : "l"(a), "l"(b)); return d;
}
union F4U { float4 f4; u64 u[2]; float f[4]; };

__device__ __forceinline__ void red4(float* addr, float4 v) {
    asm volatile("red.global.add.v4.f32 [%0], {%1,%2,%3,%4};"
                 :: "l"(addr), "f"(v.x), "f"(v.y), "f"(v.z), "f"(v.w) : "memory");
}

__device__ __forceinline__ float sigm(float x) { return 1.f / (1.f + __expf(-x)); }
__device__ __forceinline__ float softp(float x) {
    return fmaxf(x, 0.f) + __logf(1.f + __expf(-fabsf(x)));
}

// ---------------- pack concatenated projection weights ----------------
__global__ void pack_wcat(const float* __restrict__ Wf, const float* __restrict__ Ws,
                          const float* __restrict__ bf, const float* __restrict__ bs,
                          float* __restrict__ Wcat, float* __restrict__ bcat, int layer) {
    int idx = blockIdx.x * blockDim.x + threadIdx.x;
    if (idx < 512) {
        float b = 0.f;
        if (idx < 128) b = bf[layer * 128 + idx];
        else if (idx < 256) b = bs[layer * 128 + idx - 128];
        bcat[idx] = b;
    }
    if (idx >= 512 * 128) return;
    int n = idx >> 7, k = idx & 127;
    const float* W; int o, koff;
    if      (n < 128) { W = Wf; o = n;       koff = 0;   }
    else if (n < 256) { W = Ws; o = n - 128; koff = 0;   }
    else if (n < 384) { W = Wf; o = n - 256; koff = 128; }
    else              { W = Ws; o = n - 384; koff = 128; }
    Wcat[idx] = W[((size_t)(layer * 128 + o)) * 320 + koff + k];
}

// ---------------- SGEMM v2: double-buffered BK=16 ----------------
// C[M,N] = act(A[M,K] @ B[N,K]^T + bias (+res)); 128x128 tile, 256 thr, 8x8 microtile
__global__ void __launch_bounds__(256) sgemm_bt(
    const float* __restrict__ A, const float* __restrict__ B,
    const float* __restrict__ bias, const float* __restrict__ res,
    float* __restrict__ C, int M, int N, int K, int relu) {
    __shared__ float As[2][16][128];
    __shared__ float Bs[2][16][128];
    int tid = threadIdx.x;
    int m0 = blockIdx.y * 128;
    int n0 = blockIdx.x * 128;
    int tx = tid & 15, ty = tid >> 4;
    int lr = tid >> 1;            // 0..127
    int lk = (tid & 1) * 8;       // 0 or 8

    float4 ra0, ra1, rb0, rb1;
    int arow = m0 + lr;
    int brow = n0 + lr;

    // prologue load stage 0
    {
        if (arow < M) {
            ra0 = *(const float4*)(A + (size_t)arow * K + lk);
            ra1 = *(const float4*)(A + (size_t)arow * K + lk + 4);
        } else { ra0 = make_float4(0,0,0,0); ra1 = ra0; }
        rb0 = *(const float4*)(B + (size_t)brow * K + lk);
        rb1 = *(const float4*)(B + (size_t)brow * K + lk + 4);
        As[0][lk+0][lr]=ra0.x; As[0][lk+1][lr]=ra0.y; As[0][lk+2][lr]=ra0.z; As[0][lk+3][lr]=ra0.w;
        As[0][lk+4][lr]=ra1.x; As[0][lk+5][lr]=ra1.y; As[0][lk+6][lr]=ra1.z; As[0][lk+7][lr]=ra1.w;
        Bs[0][lk+0][lr]=rb0.x; Bs[0][lk+1][lr]=rb0.y; Bs[0][lk+2][lr]=rb0.z; Bs[0][lk+3][lr]=rb0.w;
        Bs[0][lk+4][lr]=rb1.x; Bs[0][lk+5][lr]=rb1.y; Bs[0][lk+6][lr]=rb1.z; Bs[0][lk+7][lr]=rb1.w;
    }
    __syncthreads();

    u64 acc[8][4];
#pragma unroll
    for (int i = 0; i < 8; i++)
#pragma unroll
        for (int j = 0; j < 4; j++) acc[i][j] = 0ull;

    int nst = K >> 4;
    for (int s = 0; s < nst; s++) {
        int b = s & 1;
        if (s + 1 < nst) {
            int k0 = (s + 1) << 4;
            if (arow < M) {
                ra0 = *(const float4*)(A + (size_t)arow * K + k0 + lk);
                ra1 = *(const float4*)(A + (size_t)arow * K + k0 + lk + 4);
            } else { ra0 = make_float4(0,0,0,0); ra1 = ra0; }
            rb0 = *(const float4*)(B + (size_t)brow * K + k0 + lk);
            rb1 = *(const float4*)(B + (size_t)brow * K + k0 + lk + 4);
        }
#pragma unroll
        for (int k = 0; k < 16; k++) {
            F4U b0, b1;
            b0.f4 = *(const float4*)&Bs[b][k][tx * 8];
            b1.f4 = *(const float4*)&Bs[b][k][tx * 8 + 4];
            float4 a0 = *(const float4*)&As[b][k][ty * 8];
            float4 a1 = *(const float4*)&As[b][k][ty * 8 + 4];
            float a[8] = {a0.x, a0.y, a0.z, a0.w, a1.x, a1.y, a1.z, a1.w};
#pragma unroll
            for (int i = 0; i < 8; i++) {
                u64 ai = pk2(a[i], a[i]);
                acc[i][0] = ffma2(ai, b0.u[0], acc[i][0]);
                acc[i][1] = ffma2(ai, b0.u[1], acc[i][1]);
                acc[i][2] = ffma2(ai, b1.u[0], acc[i][2]);
                acc[i][3] = ffma2(ai, b1.u[1], acc[i][3]);
            }
        }
        if (s + 1 < nst) {
            int nb = (s + 1) & 1;
            As[nb][lk+0][lr]=ra0.x; As[nb][lk+1][lr]=ra0.y; As[nb][lk+2][lr]=ra0.z; As[nb][lk+3][lr]=ra0.w;
            As[nb][lk+4][lr]=ra1.x; As[nb][lk+5][lr]=ra1.y; As[nb][lk+6][lr]=ra1.z; As[nb][lk+7][lr]=ra1.w;
            Bs[nb][lk+0][lr]=rb0.x; Bs[nb][lk+1][lr]=rb0.y; Bs[nb][lk+2][lr]=rb0.z; Bs[nb][lk+3][lr]=rb0.w;
            Bs[nb][lk+4][lr]=rb1.x; Bs[nb][lk+5][lr]=rb1.y; Bs[nb][lk+6][lr]=rb1.z; Bs[nb][lk+7][lr]=rb1.w;
        }
        __syncthreads();
    }

#pragma unroll
    for (int i = 0; i < 8; i++) {
        int row = m0 + ty * 8 + i;
        if (row >= M) continue;
        int n = n0 + tx * 8;
        float o[8];
#pragma unroll
        for (int j2 = 0; j2 < 4; j2++) {
            float2 v = up2(acc[i][j2]);
            o[2 * j2] = v.x; o[2 * j2 + 1] = v.y;
        }
#pragma unroll
        for (int j = 0; j < 8; j++) {
            float v = o[j] + bias[n + j];
            if (res) v += res[(size_t)row * N + n + j];
            if (relu) v = fmaxf(v, 0.f);
            o[j] = v;
        }
        *(float4*)(C + (size_t)row * N + n)     = make_float4(o[0], o[1], o[2], o[3]);
        *(float4*)(C + (size_t)row * N + n + 4) = make_float4(o[4], o[5], o[6], o[7]);
    }
}

// ---------------- edge kernel v2: register-blocked GEMM tile ----------------
// CTA tile: 64 edges x 128 cols (f AND s). 256 threads; thread = 4 edges x 8 cols.
// Persistent CTAs: weights (64KB) resident in smem, edge_attr double-buffered k-major.
// Epilogue: gather P (dst/src), add, sigmoid*softplus, red.global.add.v4.
__global__ void __launch_bounds__(256, 2) edge_kernel(
    const float* __restrict__ Pall, const int* __restrict__ ei,
    const float* __restrict__ ea, const float* __restrict__ Wf,
    const float* __restrict__ Ws, int layer, float* __restrict__ hout) {
    extern __shared__ float smem[];
    float* sWf = smem;                         // [64][128] k-major
    float* sWs = smem + 8192;                  // [64][128]
    float* sEa = smem + 16384;                 // [2][64 k][64 e]
    int*   sIdx = (int*)(smem + 16384 + 8192); // [2][128]: src 0..63, dst 64..127

    int tid = threadIdx.x;
    {
        const float* wfb = Wf + (size_t)layer * 128 * 320 + 256;
        const float* wsb = Ws + (size_t)layer * 128 * 320 + 256;
        for (int idx = tid; idx < 8192; idx += 256) {
            int k = idx >> 7, o = idx & 127;
            sWf[idx] = wfb[(size_t)o * 320 + k];
            sWs[idx] = wsb[(size_t)o * 320 + k];
        }
    }

    int eg = tid & 15;          // edges 4*eg .. 4*eg+3
    int cg = tid >> 4;          // cols 8*cg .. 8*cg+7
    int le = tid & 63;          // loader: edge index
    int kc = tid >> 6;          // loader: k-chunk of 16
    const int ntiles = NE / 64;

    // load first tile into buffer 0
    int tile = blockIdx.x;
    if (tile < ntiles) {
        int e0 = tile * 64;
        const float4* src = (const float4*)(ea + (size_t)(e0 + le) * 64 + kc * 16);
        float* dst = sEa;
#pragma unroll
        for (int j = 0; j < 4; j++) {
            float4 v = src[j];
            int kk = kc * 16 + j * 4;
            dst[(kk + 0) * 64 + le] = v.x;
            dst[(kk + 1) * 64 + le] = v.y;
            dst[(kk + 2) * 64 + le] = v.z;
            dst[(kk + 3) * 64 + le] = v.w;
        }
        if (tid < 64) sIdx[tid] = ei[e0 + tid];
        else if (tid < 128) sIdx[tid] = ei[NE + e0 + (tid - 64)];
    }
    __syncthreads();

    int buf = 0;
    int nb = gridDim.x;
    for (; tile < ntiles; tile += nb) {
        // prefetch next tile into buf^1
        int nxt = tile + nb;
        if (nxt < ntiles) {
            int e0 = nxt * 64;
            const float4* src = (const float4*)(ea + (size_t)(e0 + le) * 64 + kc * 16);
            float* dst = sEa + (buf ^ 1) * 4096;
#pragma unroll
            for (int j = 0; j < 4; j++) {
                float4 v = src[j];
                int kk = kc * 16 + j * 4;
                dst[(kk + 0) * 64 + le] = v.x;
                dst[(kk + 1) * 64 + le] = v.y;
                dst[(kk + 2) * 64 + le] = v.z;
                dst[(kk + 3) * 64 + le] = v.w;
            }
            if (tid < 64) sIdx[(buf ^ 1) * 128 + tid] = ei[e0 + tid];
            else if (tid < 128) sIdx[(buf ^ 1) * 128 + tid] = ei[NE + e0 + (tid - 64)];
        }

        // ---- compute: K=64 GEMM into 4x8x2 accumulators ----
        u64 accF[4][4], accS[4][4];
#pragma unroll
        for (int t = 0; t < 4; t++)
#pragma unroll
            for (int j = 0; j < 4; j++) { accF[t][j] = 0ull; accS[t][j] = 0ull; }

        const float* eb = sEa + buf * 4096;
        const float* wfc = sWf + cg * 8;
        const float* wsc = sWs + cg * 8;
#pragma unroll 8
        for (int k = 0; k < 64; k++) {
            F4U wfa, wfb2, wsa, wsb2, eav;
            wfa.f4  = *(const float4*)(wfc + k * 128);
            wfb2.f4 = *(const float4*)(wfc + k * 128 + 4);
            wsa.f4  = *(const float4*)(wsc + k * 128);
            wsb2.f4 = *(const float4*)(wsc + k * 128 + 4);
            eav.f4  = *(const float4*)(eb + k * 64 + eg * 4);
#pragma unroll
            for (int t = 0; t < 4; t++) {
                u64 e2 = pk2(eav.f[t], eav.f[t]);
                accF[t][0] = ffma2(wfa.u[0],  e2, accF[t][0]);
                accF[t][1] = ffma2(wfa.u[1],  e2, accF[t][1]);
                accF[t][2] = ffma2(wfb2.u[0], e2, accF[t][2]);
                accF[t][3] = ffma2(wfb2.u[1], e2, accF[t][3]);
                accS[t][0] = ffma2(wsa.u[0],  e2, accS[t][0]);
                accS[t][1] = ffma2(wsa.u[1],  e2, accS[t][1]);
                accS[t][2] = ffma2(wsb2.u[0], e2, accS[t][2]);
                accS[t][3] = ffma2(wsb2.u[1], e2, accS[t][3]);
            }
        }

        // ---- epilogue: gather P, activate, scatter ----
        int srcs[4], dsts[4];
#pragma unroll
        for (int t = 0; t < 4; t++) {
            srcs[t] = sIdx[buf * 128 + eg * 4 + t];
            dsts[t] = sIdx[buf * 128 + 64 + eg * 4 + t];
        }
        int q = cg * 2;   // float4 index within a 128-col region
#pragma unroll
        for (int t = 0; t < 4; t++) {
            const float4* pd = (const float4*)(Pall + (size_t)dsts[t] * 512);
            const float4* ps = (const float4*)(Pall + (size_t)srcs[t] * 512);
            F4U fd0, fd1, sd0, sd1, fs0, fs1, ss0, ss1;
            fd0.f4 = pd[q];      fd1.f4 = pd[q + 1];
            sd0.f4 = pd[32 + q]; sd1.f4 = pd[32 + q + 1];
            fs0.f4 = ps[64 + q]; fs1.f4 = ps[64 + q + 1];
            ss0.f4 = ps[96 + q]; ss1.f4 = ps[96 + q + 1];
            u64 fv[4], sv[4];
            fv[0] = fadd2(accF[t][0], fadd2(fd0.u[0], fs0.u[0]));
            fv[1] = fadd2(accF[t][1], fadd2(fd0.u[1], fs0.u[1]));
            fv[2] = fadd2(accF[t][2], fadd2(fd1.u[0], fs1.u[0]));
            fv[3] = fadd2(accF[t][3], fadd2(fd1.u[1], fs1.u[1]));
            sv[0] = fadd2(accS[t][0], fadd2(sd0.u[0], ss0.u[0]));
            sv[1] = fadd2(accS[t][1], fadd2(sd0.u[1], ss0.u[1]));
            sv[2] = fadd2(accS[t][2], fadd2(sd1.u[0], ss1.u[0]));
            sv[3] = fadd2(accS[t][3], fadd2(sd1.u[1], ss1.u[1]));
            float fr[8], sr[8];
#pragma unroll
            for (int j = 0; j < 4; j++) {
                float2 a = up2(fv[j]); fr[2*j] = a.x; fr[2*j+1] = a.y;
                float2 c = up2(sv[j]); sr[2*j] = c.x; sr[2*j+1] = c.y;
            }
            float4 m0, m1;
            m0.x = sigm(fr[0]) * softp(sr[0]);
            m0.y = sigm(fr[1]) * softp(sr[1]);
            m0.z = sigm(fr[2]) * softp(sr[2]);
            m0.w = sigm(fr[3]) * softp(sr[3]);
            m1.x = sigm(fr[4]) * softp(sr[4]);
            m1.y = sigm(fr[5]) * softp(sr[5]);
            m1.z = sigm(fr[6]) * softp(sr[6]);
            m1.w = sigm(fr[7]) * softp(sr[7]);
            float* hb = hout + (size_t)dsts[t] * 128 + cg * 8;
            red4(hb, m0);
            red4(hb + 4, m1);
        }
        __syncthreads();
        buf ^= 1;
    }
}

// ---------------- small utility kernels ----------------
__global__ void copy_kernel(const float* __restrict__ a, float* __restrict__ b, int n4) {
    int i = blockIdx.x * blockDim.x + threadIdx.x;
    if (i < n4) ((float4*)b)[i] = ((const float4*)a)[i];
}
__global__ void zero_kernel(float* __restrict__ p, int n) {
    int i = blockIdx.x * blockDim.x + threadIdx.x;
    if (i < n) p[i] = 0.f;
}
__global__ void pool_kernel(const float* __restrict__ h, const int* __restrict__ batch,
                            float* __restrict__ g) {
    int idx = blockIdx.x * blockDim.x + threadIdx.x;
    if (idx >= NN * 32) return;
    int node = idx >> 5, qq = idx & 31;
    float4 v = ((const float4*)h)[idx];
    red4(g + (size_t)batch[node] * 128 + qq * 4, v);
}
__global__ void out_kernel(const float* __restrict__ gf, const float* __restrict__ oW,
                           const float* __restrict__ ob, float* __restrict__ out) {
    int gidx = blockIdx.x * 8 + (threadIdx.x >> 5);
    int lane = threadIdx.x & 31;
    if (gidx >= NG) return;
    float s = 0.f;
#pragma unroll
    for (int k = lane; k < 128; k += 32) s += gf[gidx * 128 + k] * oW[k];
#pragma unroll
    for (int o = 16; o; o >>= 1) s += __shfl_down_sync(0xffffffffu, s, o);
    if (lane == 0) out[gidx] = s + ob[0];
}

// ---------------- launch ----------------
extern "C" void kernel_launch(void* const* d_in, const int* in_sizes, int n_in,
                              void* d_out, int out_size) {
    (void)in_sizes; (void)n_in; (void)out_size;
    const float* x   = (const float*)d_in[0];
    const int*   ei  = (const int*)d_in[1];
    const float* ea  = (const float*)d_in[2];
    const int*   bat = (const int*)d_in[3];
    const float* Wf  = (const float*)d_in[4];
    const float* bf  = (const float*)d_in[5];
    const float* Ws  = (const float*)d_in[6];
    const float* bs  = (const float*)d_in[7];
    const float* m1W0 = (const float*)d_in[8],  *m1b0 = (const float*)d_in[9];
    const float* m1W1 = (const float*)d_in[10], *m1b1 = (const float*)d_in[11];
    const float* m1Wp = (const float*)d_in[12], *m1bp = (const float*)d_in[13];
    const float* m2W0 = (const float*)d_in[14], *m2b0 = (const float*)d_in[15];
    const float* m2W1 = (const float*)d_in[16], *m2b1 = (const float*)d_in[17];
    const float* m2Wp = (const float*)d_in[18], *m2bp = (const float*)d_in[19];
    const float* oW   = (const float*)d_in[20], *ob   = (const float*)d_in[21];
    float* out = (float*)d_out;

    float *pH0, *pH1, *pP, *pW, *pB, *pPool, *pT0g, *pT1g, *pGf;
    cudaGetSymbolAddress((void**)&pH0,  g_h0);
    cudaGetSymbolAddress((void**)&pH1,  g_h1);
    cudaGetSymbolAddress((void**)&pP,   g_P);
    cudaGetSymbolAddress((void**)&pW,   g_Wcat);
    cudaGetSymbolAddress((void**)&pB,   g_bcat);
    cudaGetSymbolAddress((void**)&pPool, g_pool);
    cudaGetSymbolAddress((void**)&pT0g, g_t0g);
    cudaGetSymbolAddress((void**)&pT1g, g_t1g);
    cudaGetSymbolAddress((void**)&pGf,  g_gfin);

    const int EDGE_SMEM = 3 * 32768 + 1024;   // 99328 B
    cudaFuncSetAttribute(edge_kernel, cudaFuncAttributeMaxDynamicSharedMemorySize, EDGE_SMEM);

    const int MB = (NN + 127) / 128;   // 391
    const int EGRID = 296;             // ~2 per SM persistent

    // --- CGConv layer 0 ---
    pack_wcat<<<(512 * 128 + 255) / 256, 256>>>(Wf, Ws, bf, bs, pW, pB, 0);
    sgemm_bt<<<dim3(4, MB), 256>>>(x, pW, pB, nullptr, pP, NN, 512, 128, 0);
    copy_kernel<<<(NN * 32 + 255) / 256, 256>>>(x, pH0, NN * 32);
    edge_kernel<<<EGRID, 256, EDGE_SMEM>>>(pP, ei, ea, Wf, Ws, 0, pH0);

    // --- CGConv layer 1 ---
    pack_wcat<<<(512 * 128 + 255) / 256, 256>>>(Wf, Ws, bf, bs, pW, pB, 1);
    sgemm_bt<<<dim3(4, MB), 256>>>(pH0, pW, pB, nullptr, pP, NN, 512, 128, 0);
    copy_kernel<<<(NN * 32 + 255) / 256, 256>>>(pH0, pH1, NN * 32);
    edge_kernel<<<EGRID, 256, EDGE_SMEM>>>(pP, ei, ea, Wf, Ws, 1, pH1);

    // --- node MLP (residual) ---
    float* t0 = pP;
    float* t1 = pP + (size_t)NN * 256;
    sgemm_bt<<<dim3(2, MB), 256>>>(pH1, m1W0, m1b0, nullptr, t0, NN, 256, 128, 1);
    sgemm_bt<<<dim3(2, MB), 256>>>(t0, m1W1, m1b1, nullptr, t1, NN, 256, 256, 1);
    sgemm_bt<<<dim3(1, MB), 256>>>(t1, m1Wp, m1bp, pH1, pH0, NN, 128, 256, 0);

    // --- global add pool ---
    zero_kernel<<<(NG * 128 + 255) / 256, 256>>>(pPool, NG * 128);
    pool_kernel<<<(NN * 32 + 255) / 256, 256>>>(pH0, bat, pPool);

    // --- graph MLP (residual) + head ---
    sgemm_bt<<<dim3(2, 4), 256>>>(pPool, m2W0, m2b0, nullptr, pT0g, NG, 256, 128, 1);
    sgemm_bt<<<dim3(2, 4), 256>>>(pT0g, m2W1, m2b1, nullptr, pT1g, NG, 256, 256, 1);
    sgemm_bt<<<dim3(1, 4), 256>>>(pT1g, m2Wp, m2bp, pPool, pGf, NG, 128, 256, 0);
    out_kernel<<<64, 256>>>(pGf, oW, ob, out);
}

// round 5
// speedup vs baseline: 1.2047x; 1.2047x over previous
#include <cuda_runtime.h>

#define NN 50000
#define NE 800000
#define NG 512

// ---------------- device scratch (static, no runtime alloc) ----------------
__device__ float g_h0[NN * 128];
__device__ float g_h1[NN * 128];
__device__ float g_P [NN * 512];
__device__ float g_Wcat[512 * 128];
__device__ float g_bcat[512];
__device__ float g_pool[NG * 128];
__device__ float g_t0g[NG * 256];
__device__ float g_t1g[NG * 256];
__device__ float g_gfin[NG * 128];

// ---------------- f32x2 helpers ----------------
typedef unsigned long long u64;
__device__ __forceinline__ u64 pk2(float lo, float hi) {
    u64 r; asm("mov.b64 %0,{%1,%2};" : "=l"(r) : "f"(lo), "f"(hi)); return r;
}
__device__ __forceinline__ float2 up2(u64 v) {
    float2 r; asm("mov.b64 {%0,%1},%2;" : "=f"(r.x), "=f"(r.y) : "l"(v)); return r;
}
__device__ __forceinline__ u64 ffma2(u64 a, u64 b, u64 c) {
    u64 d; asm("fma.rn.f32x2 %0,%1,%2,%3;" : "=l"(d) : "l"(a), "l"(b), "l"(c)); return d;
}
__device__ __forceinline__ u64 fadd2(u64 a, u64 b) {
    u64 d; asm("add.rn.f32x2 %0,%1,%2;" : "=l"(d) : "l"(a), "l"(b)); return d;
}
union F4U { float4 f4; u64 u[2]; float f[4]; };

__device__ __forceinline__ void red4(float* addr, float4 v) {
    asm volatile("red.global.add.v4.f32 [%0], {%1,%2,%3,%4};"
                 :: "l"(addr), "f"(v.x), "f"(v.y), "f"(v.z), "f"(v.w) : "memory");
}
__device__ __forceinline__ void cpasync16(unsigned saddr, const void* gaddr) {
    asm volatile("cp.async.cg.shared.global [%0], [%1], 16;" :: "r"(saddr), "l"(gaddr));
}
__device__ __forceinline__ void cpcommit() { asm volatile("cp.async.commit_group;"); }
__device__ __forceinline__ void cpwait0()  { asm volatile("cp.async.wait_group 0;"); }

__device__ __forceinline__ float sigm(float x) { return 1.f / (1.f + __expf(-x)); }
__device__ __forceinline__ float softp(float x) {
    return fmaxf(x, 0.f) + __logf(1.f + __expf(-fabsf(x)));
}

// ---------------- pack concatenated projection weights ----------------
__global__ void pack_wcat(const float* __restrict__ Wf, const float* __restrict__ Ws,
                          const float* __restrict__ bf, const float* __restrict__ bs,
                          float* __restrict__ Wcat, float* __restrict__ bcat, int layer) {
    int idx = blockIdx.x * blockDim.x + threadIdx.x;
    if (idx < 512) {
        float b = 0.f;
        if (idx < 128) b = bf[layer * 128 + idx];
        else if (idx < 256) b = bs[layer * 128 + idx - 128];
        bcat[idx] = b;
    }
    if (idx >= 512 * 128) return;
    int n = idx >> 7, k = idx & 127;
    const float* W; int o, koff;
    if      (n < 128) { W = Wf; o = n;       koff = 0;   }
    else if (n < 256) { W = Ws; o = n - 128; koff = 0;   }
    else if (n < 384) { W = Wf; o = n - 256; koff = 128; }
    else              { W = Ws; o = n - 384; koff = 128; }
    Wcat[idx] = W[((size_t)(layer * 128 + o)) * 320 + koff + k];
}

// ---------------- SGEMM (R1 version, BK=8) ----------------
__global__ void __launch_bounds__(256) sgemm_bt(
    const float* __restrict__ A, const float* __restrict__ B,
    const float* __restrict__ bias, const float* __restrict__ res,
    float* __restrict__ C, int M, int N, int K, int relu) {
    __shared__ float As[8][128];
    __shared__ float Bs[8][128];
    int tid = threadIdx.x;
    int m0 = blockIdx.y * 128;
    int n0 = blockIdx.x * 128;
    int tx = tid & 15, ty = tid >> 4;
    int lr = tid >> 1;
    int lk = (tid & 1) * 4;

    u64 acc[8][4];
#pragma unroll
    for (int i = 0; i < 8; i++)
#pragma unroll
        for (int j = 0; j < 4; j++) acc[i][j] = 0ull;

    for (int k0 = 0; k0 < K; k0 += 8) {
        float4 av = make_float4(0.f, 0.f, 0.f, 0.f);
        int arow = m0 + lr;
        if (arow < M) av = *(const float4*)(A + (size_t)arow * K + k0 + lk);
        As[lk + 0][lr] = av.x; As[lk + 1][lr] = av.y;
        As[lk + 2][lr] = av.z; As[lk + 3][lr] = av.w;
        float4 bv = *(const float4*)(B + (size_t)(n0 + lr) * K + k0 + lk);
        Bs[lk + 0][lr] = bv.x; Bs[lk + 1][lr] = bv.y;
        Bs[lk + 2][lr] = bv.z; Bs[lk + 3][lr] = bv.w;
        __syncthreads();
#pragma unroll
        for (int k = 0; k < 8; k++) {
            F4U b0, b1;
            b0.f4 = *(const float4*)&Bs[k][tx * 8];
            b1.f4 = *(const float4*)&Bs[k][tx * 8 + 4];
            float4 a0 = *(const float4*)&As[k][ty * 8];
            float4 a1 = *(const float4*)&As[k][ty * 8 + 4];
            float a[8] = {a0.x, a0.y, a0.z, a0.w, a1.x, a1.y, a1.z, a1.w};
#pragma unroll
            for (int i = 0; i < 8; i++) {
                u64 ai = pk2(a[i], a[i]);
                acc[i][0] = ffma2(ai, b0.u[0], acc[i][0]);
                acc[i][1] = ffma2(ai, b0.u[1], acc[i][1]);
                acc[i][2] = ffma2(ai, b1.u[0], acc[i][2]);
                acc[i][3] = ffma2(ai, b1.u[1], acc[i][3]);
            }
        }
        __syncthreads();
    }

#pragma unroll
    for (int i = 0; i < 8; i++) {
        int row = m0 + ty * 8 + i;
        if (row >= M) continue;
        int n = n0 + tx * 8;
        float o[8];
#pragma unroll
        for (int j2 = 0; j2 < 4; j2++) {
            float2 v = up2(acc[i][j2]);
            o[2 * j2] = v.x; o[2 * j2 + 1] = v.y;
        }
#pragma unroll
        for (int j = 0; j < 8; j++) {
            float v = o[j] + bias[n + j];
            if (res) v += res[(size_t)row * N + n + j];
            if (relu) v = fmaxf(v, 0.f);
            o[j] = v;
        }
        *(float4*)(C + (size_t)row * N + n)     = make_float4(o[0], o[1], o[2], o[3]);
        *(float4*)(C + (size_t)row * N + n + 4) = make_float4(o[4], o[5], o[6], o[7]);
    }
}

// ---------------- edge kernel v3 ----------------
// Per warp iteration: 8 edges, all 128 output cols, f AND s.
// Lane owns cols 4*lane..4*lane+3. Weights resident in smem (64KB, k-major).
// edge_attr double-buffered per-warp in smem via cp.async (k-contiguous rows).
// Inner loop (2 k-steps): 4 LDS.128 weights + 8 LDS.64 broadcasts -> 64 FFMA2.
__global__ void __launch_bounds__(256, 2) edge_kernel(
    const float* __restrict__ Pall, const int* __restrict__ ei,
    const float* __restrict__ ea, const float* __restrict__ Wf,
    const float* __restrict__ Ws, int layer, float* __restrict__ hout) {
    extern __shared__ float smem[];
    float* sWf = smem;                 // [64][128] k-major: sWf[k*128+o]
    float* sWs = smem + 8192;
    float* sEa = smem + 16384;         // [8 warps][2 bufs][8 edges][64 k]

    int tid = threadIdx.x;
    {
        const float* wfb = Wf + (size_t)layer * 128 * 320 + 256;
        const float* wsb = Ws + (size_t)layer * 128 * 320 + 256;
        for (int idx = tid; idx < 8192; idx += 256) {
            int k = idx >> 7, o = idx & 127;
            sWf[idx] = wfb[(size_t)o * 320 + k];
            sWs[idx] = wsb[(size_t)o * 320 + k];
        }
    }
    __syncthreads();

    int w = tid >> 5, lane = tid & 31;
    float* myEa = sEa + (size_t)w * 1024;   // two 512-float buffers
    unsigned myEaAddr = (unsigned)__cvta_generic_to_shared(myEa);
    const float4* wf4 = (const float4*)sWf;
    const float4* ws4 = (const float4*)sWs;

    int gw = blockIdx.x * 8 + w;
    int nw = gridDim.x * 8;
    const int ngr = NE / 8;   // 100000

    int g = gw;
    int idx_cur = 0;
    if (g < ngr) {
        // preload buf0
        const float4* gsrc = (const float4*)(ea + (size_t)g * 8 * 64);
#pragma unroll
        for (int j = 0; j < 4; j++)
            cpasync16(myEaAddr + (j * 32 + lane) * 16, gsrc + j * 32 + lane);
        cpcommit();
        if (lane < 16) idx_cur = ei[(lane < 8 ? 0 : NE) + g * 8 + (lane & 7)];
        cpwait0();
    }
    __syncwarp();

    int buf = 0;
    for (; g < ngr; g += nw) {
        int gn = g + nw;
        int idx_next = 0;
        if (gn < ngr) {
            const float4* gsrc = (const float4*)(ea + (size_t)gn * 8 * 64);
            unsigned dst = myEaAddr + (buf ^ 1) * 2048;
#pragma unroll
            for (int j = 0; j < 4; j++)
                cpasync16(dst + (j * 32 + lane) * 16, gsrc + j * 32 + lane);
            cpcommit();
            if (lane < 16) idx_next = ei[(lane < 8 ? 0 : NE) + gn * 8 + (lane & 7)];
        }

        // ---- init acc from P gathers ----
        u64 aF[8][2], aS[8][2];
        int dsts[8];
#pragma unroll
        for (int t = 0; t < 8; t++) {
            int s = __shfl_sync(0xffffffffu, idx_cur, t);
            int d = __shfl_sync(0xffffffffu, idx_cur, 8 + t);
            dsts[t] = d;
            const float4* pd = (const float4*)(Pall + (size_t)d * 512);
            const float4* ps = (const float4*)(Pall + (size_t)s * 512);
            F4U fd, sd, fs, ss;
            fd.f4 = pd[lane];
            sd.f4 = pd[32 + lane];
            fs.f4 = ps[64 + lane];
            ss.f4 = ps[96 + lane];
            aF[t][0] = fadd2(fd.u[0], fs.u[0]); aF[t][1] = fadd2(fd.u[1], fs.u[1]);
            aS[t][0] = fadd2(sd.u[0], ss.u[0]); aS[t][1] = fadd2(sd.u[1], ss.u[1]);
        }

        // ---- K=64 accumulate, 2 k per step ----
        const float* eb = myEa + buf * 512;
#pragma unroll 4
        for (int k = 0; k < 64; k += 2) {
            F4U wf0, wf1, ws0, ws1;
            wf0.f4 = wf4[k * 32 + lane];
            wf1.f4 = wf4[(k + 1) * 32 + lane];
            ws0.f4 = ws4[k * 32 + lane];
            ws1.f4 = ws4[(k + 1) * 32 + lane];
#pragma unroll
            for (int t = 0; t < 8; t++) {
                float2 e2 = *(const float2*)(eb + t * 64 + k);   // broadcast
                u64 ex = pk2(e2.x, e2.x);
                u64 ey = pk2(e2.y, e2.y);
                aF[t][0] = ffma2(wf0.u[0], ex, aF[t][0]);
                aF[t][1] = ffma2(wf0.u[1], ex, aF[t][1]);
                aS[t][0] = ffma2(ws0.u[0], ex, aS[t][0]);
                aS[t][1] = ffma2(ws0.u[1], ex, aS[t][1]);
                aF[t][0] = ffma2(wf1.u[0], ey, aF[t][0]);
                aF[t][1] = ffma2(wf1.u[1], ey, aF[t][1]);
                aS[t][0] = ffma2(ws1.u[0], ey, aS[t][0]);
                aS[t][1] = ffma2(ws1.u[1], ey, aS[t][1]);
            }
        }

        // ---- activate + scatter ----
#pragma unroll
        for (int t = 0; t < 8; t++) {
            float2 f0 = up2(aF[t][0]), f1 = up2(aF[t][1]);
            float2 s0 = up2(aS[t][0]), s1 = up2(aS[t][1]);
            float4 m;
            m.x = sigm(f0.x) * softp(s0.x);
            m.y = sigm(f0.y) * softp(s0.y);
            m.z = sigm(f1.x) * softp(s1.x);
            m.w = sigm(f1.y) * softp(s1.y);
            red4(hout + (size_t)dsts[t] * 128 + lane * 4, m);
        }

        cpwait0();
        __syncwarp();
        idx_cur = idx_next;
        buf ^= 1;
    }
}

// ---------------- small utility kernels ----------------
__global__ void copy_kernel(const float* __restrict__ a, float* __restrict__ b, int n4) {
    int i = blockIdx.x * blockDim.x + threadIdx.x;
    if (i < n4) ((float4*)b)[i] = ((const float4*)a)[i];
}
__global__ void zero_kernel(float* __restrict__ p, int n) {
    int i = blockIdx.x * blockDim.x + threadIdx.x;
    if (i < n) p[i] = 0.f;
}
__global__ void pool_kernel(const float* __restrict__ h, const int* __restrict__ batch,
                            float* __restrict__ g) {
    int idx = blockIdx.x * blockDim.x + threadIdx.x;
    if (idx >= NN * 32) return;
    int node = idx >> 5, qq = idx & 31;
    float4 v = ((const float4*)h)[idx];
    red4(g + (size_t)batch[node] * 128 + qq * 4, v);
}
__global__ void out_kernel(const float* __restrict__ gf, const float* __restrict__ oW,
                           const float* __restrict__ ob, float* __restrict__ out) {
    int gidx = blockIdx.x * 8 + (threadIdx.x >> 5);
    int lane = threadIdx.x & 31;
    if (gidx >= NG) return;
    float s = 0.f;
#pragma unroll
    for (int k = lane; k < 128; k += 32) s += gf[gidx * 128 + k] * oW[k];
#pragma unroll
    for (int o = 16; o; o >>= 1) s += __shfl_down_sync(0xffffffffu, s, o);
    if (lane == 0) out[gidx] = s + ob[0];
}

// ---------------- launch ----------------
extern "C" void kernel_launch(void* const* d_in, const int* in_sizes, int n_in,
                              void* d_out, int out_size) {
    (void)in_sizes; (void)n_in; (void)out_size;
    const float* x   = (const float*)d_in[0];
    const int*   ei  = (const int*)d_in[1];
    const float* ea  = (const float*)d_in[2];
    const int*   bat = (const int*)d_in[3];
    const float* Wf  = (const float*)d_in[4];
    const float* bf  = (const float*)d_in[5];
    const float* Ws  = (const float*)d_in[6];
    const float* bs  = (const float*)d_in[7];
    const float* m1W0 = (const float*)d_in[8],  *m1b0 = (const float*)d_in[9];
    const float* m1W1 = (const float*)d_in[10], *m1b1 = (const float*)d_in[11];
    const float* m1Wp = (const float*)d_in[12], *m1bp = (const float*)d_in[13];
    const float* m2W0 = (const float*)d_in[14], *m2b0 = (const float*)d_in[15];
    const float* m2W1 = (const float*)d_in[16], *m2b1 = (const float*)d_in[17];
    const float* m2Wp = (const float*)d_in[18], *m2bp = (const float*)d_in[19];
    const float* oW   = (const float*)d_in[20], *ob   = (const float*)d_in[21];
    float* out = (float*)d_out;

    float *pH0, *pH1, *pP, *pW, *pB, *pPool, *pT0g, *pT1g, *pGf;
    cudaGetSymbolAddress((void**)&pH0,  g_h0);
    cudaGetSymbolAddress((void**)&pH1,  g_h1);
    cudaGetSymbolAddress((void**)&pP,   g_P);
    cudaGetSymbolAddress((void**)&pW,   g_Wcat);
    cudaGetSymbolAddress((void**)&pB,   g_bcat);
    cudaGetSymbolAddress((void**)&pPool, g_pool);
    cudaGetSymbolAddress((void**)&pT0g, g_t0g);
    cudaGetSymbolAddress((void**)&pT1g, g_t1g);
    cudaGetSymbolAddress((void**)&pGf,  g_gfin);

    // smem: weights 64KB + ea 8 warps * 2 bufs * 2KB = 32KB  -> 96KB
    const int EDGE_SMEM = 65536 + 32768;   // 98304 B
    cudaFuncSetAttribute(edge_kernel, cudaFuncAttributeMaxDynamicSharedMemorySize, EDGE_SMEM);

    const int MB = (NN + 127) / 128;   // 391
    const int EGRID = 296;

    // --- CGConv layer 0 ---
    pack_wcat<<<(512 * 128 + 255) / 256, 256>>>(Wf, Ws, bf, bs, pW, pB, 0);
    sgemm_bt<<<dim3(4, MB), 256>>>(x, pW, pB, nullptr, pP, NN, 512, 128, 0);
    copy_kernel<<<(NN * 32 + 255) / 256, 256>>>(x, pH0, NN * 32);
    edge_kernel<<<EGRID, 256, EDGE_SMEM>>>(pP, ei, ea, Wf, Ws, 0, pH0);

    // --- CGConv layer 1 ---
    pack_wcat<<<(512 * 128 + 255) / 256, 256>>>(Wf, Ws, bf, bs, pW, pB, 1);
    sgemm_bt<<<dim3(4, MB), 256>>>(pH0, pW, pB, nullptr, pP, NN, 512, 128, 0);
    copy_kernel<<<(NN * 32 + 255) / 256, 256>>>(pH0, pH1, NN * 32);
    edge_kernel<<<EGRID, 256, EDGE_SMEM>>>(pP, ei, ea, Wf, Ws, 1, pH1);

    // --- node MLP (residual) ---
    float* t0 = pP;
    float* t1 = pP + (size_t)NN * 256;
    sgemm_bt<<<dim3(2, MB), 256>>>(pH1, m1W0, m1b0, nullptr, t0, NN, 256, 128, 1);
    sgemm_bt<<<dim3(2, MB), 256>>>(t0, m1W1, m1b1, nullptr, t1, NN, 256, 256, 1);
    sgemm_bt<<<dim3(1, MB), 256>>>(t1, m1Wp, m1bp, pH1, pH0, NN, 128, 256, 0);

    // --- global add pool ---
    zero_kernel<<<(NG * 128 + 255) / 256, 256>>>(pPool, NG * 128);
    pool_kernel<<<(NN * 32 + 255) / 256, 256>>>(pH0, bat, pPool);

    // --- graph MLP (residual) + head ---
    sgemm_bt<<<dim3(2, 4), 256>>>(pPool, m2W0, m2b0, nullptr, pT0g, NG, 256, 128, 1);
    sgemm_bt<<<dim3(2, 4), 256>>>(pT0g, m2W1, m2b1, nullptr, pT1g, NG, 256, 256, 1);
    sgemm_bt<<<dim3(1, 4), 256>>>(pT1g, m2Wp, m2bp, pPool, pGf, NG, 128, 256, 0);
    out_kernel<<<64, 256>>>(pGf, oW, ob, out);
}

// round 6
// speedup vs baseline: 1.2268x; 1.0184x over previous
#include <cuda_runtime.h>

#define NN 50000
#define NE 800000
#define NG 512

// ---------------- device scratch (static, no runtime alloc) ----------------
__device__ float g_h0[NN * 128];
__device__ float g_h1[NN * 128];
__device__ float g_P [NN * 512];
__device__ float g_Wcat[512 * 128];
__device__ float g_bcat[512];
__device__ float g_pool[NG * 128];
__device__ float g_t0g[NG * 256];
__device__ float g_t1g[NG * 256];
__device__ float g_gfin[NG * 128];

// ---------------- f32x2 helpers ----------------
typedef unsigned long long u64;
__device__ __forceinline__ u64 pk2(float lo, float hi) {
    u64 r; asm("mov.b64 %0,{%1,%2};" : "=l"(r) : "f"(lo), "f"(hi)); return r;
}
__device__ __forceinline__ float2 up2(u64 v) {
    float2 r; asm("mov.b64 {%0,%1},%2;" : "=f"(r.x), "=f"(r.y) : "l"(v)); return r;
}
__device__ __forceinline__ u64 ffma2(u64 a, u64 b, u64 c) {
    u64 d; asm("fma.rn.f32x2 %0,%1,%2,%3;" : "=l"(d) : "l"(a), "l"(b), "l"(c)); return d;
}
__device__ __forceinline__ u64 fadd2(u64 a, u64 b) {
    u64 d; asm("add.rn.f32x2 %0,%1,%2;" : "=l"(d) : "l"(a), "l"(b)); return d;
}
union F4U { float4 f4; u64 u[2]; float f[4]; };

__device__ __forceinline__ void red4(float* addr, float4 v) {
    asm volatile("red.global.add.v4.f32 [%0], {%1,%2,%3,%4};"
                 :: "l"(addr), "f"(v.x), "f"(v.y), "f"(v.z), "f"(v.w) : "memory");
}
__device__ __forceinline__ void cpasync16(unsigned saddr, const void* gaddr) {
    asm volatile("cp.async.cg.shared.global [%0], [%1], 16;" :: "r"(saddr), "l"(gaddr));
}
__device__ __forceinline__ void cpcommit() { asm volatile("cp.async.commit_group;"); }
__device__ __forceinline__ void cpwait0()  { asm volatile("cp.async.wait_group 0;"); }
__device__ __forceinline__ void pref_l1(const void* p) {
    asm volatile("prefetch.global.L1 [%0];" :: "l"(p));
}

__device__ __forceinline__ float sigm(float x) { return 1.f / (1.f + __expf(-x)); }
__device__ __forceinline__ float softp(float x) {
    return fmaxf(x, 0.f) + __logf(1.f + __expf(-fabsf(x)));
}

// ---------------- pack concatenated projection weights ----------------
__global__ void pack_wcat(const float* __restrict__ Wf, const float* __restrict__ Ws,
                          const float* __restrict__ bf, const float* __restrict__ bs,
                          float* __restrict__ Wcat, float* __restrict__ bcat, int layer) {
    int idx = blockIdx.x * blockDim.x + threadIdx.x;
    if (idx < 512) {
        float b = 0.f;
        if (idx < 128) b = bf[layer * 128 + idx];
        else if (idx < 256) b = bs[layer * 128 + idx - 128];
        bcat[idx] = b;
    }
    if (idx >= 512 * 128) return;
    int n = idx >> 7, k = idx & 127;
    const float* W; int o, koff;
    if      (n < 128) { W = Wf; o = n;       koff = 0;   }
    else if (n < 256) { W = Ws; o = n - 128; koff = 0;   }
    else if (n < 384) { W = Wf; o = n - 256; koff = 128; }
    else              { W = Ws; o = n - 384; koff = 128; }
    Wcat[idx] = W[((size_t)(layer * 128 + o)) * 320 + koff + k];
}

// ---------------- SGEMM (R1 version, BK=8) ----------------
__global__ void __launch_bounds__(256) sgemm_bt(
    const float* __restrict__ A, const float* __restrict__ B,
    const float* __restrict__ bias, const float* __restrict__ res,
    float* __restrict__ C, int M, int N, int K, int relu) {
    __shared__ float As[8][128];
    __shared__ float Bs[8][128];
    int tid = threadIdx.x;
    int m0 = blockIdx.y * 128;
    int n0 = blockIdx.x * 128;
    int tx = tid & 15, ty = tid >> 4;
    int lr = tid >> 1;
    int lk = (tid & 1) * 4;

    u64 acc[8][4];
#pragma unroll
    for (int i = 0; i < 8; i++)
#pragma unroll
        for (int j = 0; j < 4; j++) acc[i][j] = 0ull;

    for (int k0 = 0; k0 < K; k0 += 8) {
        float4 av = make_float4(0.f, 0.f, 0.f, 0.f);
        int arow = m0 + lr;
        if (arow < M) av = *(const float4*)(A + (size_t)arow * K + k0 + lk);
        As[lk + 0][lr] = av.x; As[lk + 1][lr] = av.y;
        As[lk + 2][lr] = av.z; As[lk + 3][lr] = av.w;
        float4 bv = *(const float4*)(B + (size_t)(n0 + lr) * K + k0 + lk);
        Bs[lk + 0][lr] = bv.x; Bs[lk + 1][lr] = bv.y;
        Bs[lk + 2][lr] = bv.z; Bs[lk + 3][lr] = bv.w;
        __syncthreads();
#pragma unroll
        for (int k = 0; k < 8; k++) {
            F4U b0, b1;
            b0.f4 = *(const float4*)&Bs[k][tx * 8];
            b1.f4 = *(const float4*)&Bs[k][tx * 8 + 4];
            float4 a0 = *(const float4*)&As[k][ty * 8];
            float4 a1 = *(const float4*)&As[k][ty * 8 + 4];
            float a[8] = {a0.x, a0.y, a0.z, a0.w, a1.x, a1.y, a1.z, a1.w};
#pragma unroll
            for (int i = 0; i < 8; i++) {
                u64 ai = pk2(a[i], a[i]);
                acc[i][0] = ffma2(ai, b0.u[0], acc[i][0]);
                acc[i][1] = ffma2(ai, b0.u[1], acc[i][1]);
                acc[i][2] = ffma2(ai, b1.u[0], acc[i][2]);
                acc[i][3] = ffma2(ai, b1.u[1], acc[i][3]);
            }
        }
        __syncthreads();
    }

#pragma unroll
    for (int i = 0; i < 8; i++) {
        int row = m0 + ty * 8 + i;
        if (row >= M) continue;
        int n = n0 + tx * 8;
        float o[8];
#pragma unroll
        for (int j2 = 0; j2 < 4; j2++) {
            float2 v = up2(acc[i][j2]);
            o[2 * j2] = v.x; o[2 * j2 + 1] = v.y;
        }
#pragma unroll
        for (int j = 0; j < 8; j++) {
            float v = o[j] + bias[n + j];
            if (res) v += res[(size_t)row * N + n + j];
            if (relu) v = fmaxf(v, 0.f);
            o[j] = v;
        }
        *(float4*)(C + (size_t)row * N + n)     = make_float4(o[0], o[1], o[2], o[3]);
        *(float4*)(C + (size_t)row * N + n + 4) = make_float4(o[4], o[5], o[6], o[7]);
    }
}

// ---------------- edge kernel v4: v3 + P-gather L1 prefetch, idx distance-2 ----------------
__global__ void __launch_bounds__(256, 2) edge_kernel(
    const float* __restrict__ Pall, const int* __restrict__ ei,
    const float* __restrict__ ea, const float* __restrict__ Wf,
    const float* __restrict__ Ws, int layer, float* __restrict__ hout) {
    extern __shared__ float smem[];
    float* sWf = smem;                 // [64][128] k-major
    float* sWs = smem + 8192;
    float* sEa = smem + 16384;         // [8 warps][2 bufs][8 edges][64 k]

    int tid = threadIdx.x;
    {
        const float* wfb = Wf + (size_t)layer * 128 * 320 + 256;
        const float* wsb = Ws + (size_t)layer * 128 * 320 + 256;
        for (int idx = tid; idx < 8192; idx += 256) {
            int k = idx >> 7, o = idx & 127;
            sWf[idx] = wfb[(size_t)o * 320 + k];
            sWs[idx] = wsb[(size_t)o * 320 + k];
        }
    }
    __syncthreads();

    int w = tid >> 5, lane = tid & 31;
    float* myEa = sEa + (size_t)w * 1024;
    unsigned myEaAddr = (unsigned)__cvta_generic_to_shared(myEa);
    const float4* wf4 = (const float4*)sWf;
    const float4* ws4 = (const float4*)sWs;

    int gw = blockIdx.x * 8 + w;
    int nw = gridDim.x * 8;
    const int ngr = NE / 8;   // 100000

    // lines l = lane*4+j: e = l>>4, isSrc = (l>>3)&1, seg = l&7
    // dst node lines at P+node*512 + seg*32 ; src lines at +256 + seg*32
#define PREFETCH_P(IDXREG) do {                                              \
        _Pragma("unroll")                                                    \
        for (int j = 0; j < 4; j++) {                                        \
            int l = lane * 4 + j;                                            \
            int e_ = l >> 4;                                                 \
            int isSrc_ = (l >> 3) & 1;                                       \
            int seg_ = l & 7;                                                \
            int node_ = __shfl_sync(0xffffffffu, (IDXREG),                   \
                                    isSrc_ ? e_ : 8 + e_);                   \
            pref_l1(Pall + (size_t)node_ * 512 + isSrc_ * 256 + seg_ * 32);  \
        } } while (0)

    int g = gw;
    int idx_cur = 0, idx_next = 0;
    if (g < ngr) {
        const float4* gsrc = (const float4*)(ea + (size_t)g * 8 * 64);
#pragma unroll
        for (int j = 0; j < 4; j++)
            cpasync16(myEaAddr + (j * 32 + lane) * 16, gsrc + j * 32 + lane);
        cpcommit();
        if (lane < 16) idx_cur = ei[(lane < 8 ? 0 : NE) + g * 8 + (lane & 7)];
        int gn = g + nw;
        if (gn < ngr && lane < 16) idx_next = ei[(lane < 8 ? 0 : NE) + gn * 8 + (lane & 7)];
        PREFETCH_P(idx_cur);   // warm first group (cold start only)
        cpwait0();
    }
    __syncwarp();

    int buf = 0;
    for (; g < ngr; g += nw) {
        int gn = g + nw;
        if (gn < ngr) {
            const float4* gsrc = (const float4*)(ea + (size_t)gn * 8 * 64);
            unsigned dst = myEaAddr + (buf ^ 1) * 2048;
#pragma unroll
            for (int j = 0; j < 4; j++)
                cpasync16(dst + (j * 32 + lane) * 16, gsrc + j * 32 + lane);
            cpcommit();
            PREFETCH_P(idx_next);          // idx_next arrived one iter ago
        }
        int gf = g + 2 * nw;
        int idx_far = 0;
        if (gf < ngr && lane < 16)
            idx_far = ei[(lane < 8 ? 0 : NE) + gf * 8 + (lane & 7)];

        // ---- init acc from P gathers (prefetched last iter -> L1) ----
        u64 aF[8][2], aS[8][2];
        int dsts[8];
#pragma unroll
        for (int t = 0; t < 8; t++) {
            int s = __shfl_sync(0xffffffffu, idx_cur, t);
            int d = __shfl_sync(0xffffffffu, idx_cur, 8 + t);
            dsts[t] = d;
            const float4* pd = (const float4*)(Pall + (size_t)d * 512);
            const float4* ps = (const float4*)(Pall + (size_t)s * 512);
            F4U fd, sd, fs, ss;
            fd.f4 = pd[lane];
            sd.f4 = pd[32 + lane];
            fs.f4 = ps[64 + lane];
            ss.f4 = ps[96 + lane];
            aF[t][0] = fadd2(fd.u[0], fs.u[0]); aF[t][1] = fadd2(fd.u[1], fs.u[1]);
            aS[t][0] = fadd2(sd.u[0], ss.u[0]); aS[t][1] = fadd2(sd.u[1], ss.u[1]);
        }

        // ---- K=64 accumulate, 2 k per step ----
        const float* eb = myEa + buf * 512;
#pragma unroll 4
        for (int k = 0; k < 64; k += 2) {
            F4U wf0, wf1, ws0, ws1;
            wf0.f4 = wf4[k * 32 + lane];
            wf1.f4 = wf4[(k + 1) * 32 + lane];
            ws0.f4 = ws4[k * 32 + lane];
            ws1.f4 = ws4[(k + 1) * 32 + lane];
#pragma unroll
            for (int t = 0; t < 8; t++) {
                float2 e2 = *(const float2*)(eb + t * 64 + k);
                u64 ex = pk2(e2.x, e2.x);
                u64 ey = pk2(e2.y, e2.y);
                aF[t][0] = ffma2(wf0.u[0], ex, aF[t][0]);
                aF[t][1] = ffma2(wf0.u[1], ex, aF[t][1]);
                aS[t][0] = ffma2(ws0.u[0], ex, aS[t][0]);
                aS[t][1] = ffma2(ws0.u[1], ex, aS[t][1]);
                aF[t][0] = ffma2(wf1.u[0], ey, aF[t][0]);
                aF[t][1] = ffma2(wf1.u[1], ey, aF[t][1]);
                aS[t][0] = ffma2(ws1.u[0], ey, aS[t][0]);
                aS[t][1] = ffma2(ws1.u[1], ey, aS[t][1]);
            }
        }

        // ---- activate + scatter ----
#pragma unroll
        for (int t = 0; t < 8; t++) {
            float2 f0 = up2(aF[t][0]), f1 = up2(aF[t][1]);
            float2 s0 = up2(aS[t][0]), s1 = up2(aS[t][1]);
            float4 m;
            m.x = sigm(f0.x) * softp(s0.x);
            m.y = sigm(f0.y) * softp(s0.y);
            m.z = sigm(f1.x) * softp(s1.x);
            m.w = sigm(f1.y) * softp(s1.y);
            red4(hout + (size_t)dsts[t] * 128 + lane * 4, m);
        }

        cpwait0();
        __syncwarp();
        idx_cur = idx_next;
        idx_next = idx_far;
        buf ^= 1;
    }
#undef PREFETCH_P
}

// ---------------- small utility kernels ----------------
__global__ void copy_kernel(const float* __restrict__ a, float* __restrict__ b, int n4) {
    int i = blockIdx.x * blockDim.x + threadIdx.x;
    if (i < n4) ((float4*)b)[i] = ((const float4*)a)[i];
}
__global__ void zero_kernel(float* __restrict__ p, int n) {
    int i = blockIdx.x * blockDim.x + threadIdx.x;
    if (i < n) p[i] = 0.f;
}
__global__ void pool_kernel(const float* __restrict__ h, const int* __restrict__ batch,
                            float* __restrict__ g) {
    int idx = blockIdx.x * blockDim.x + threadIdx.x;
    if (idx >= NN * 32) return;
    int node = idx >> 5, qq = idx & 31;
    float4 v = ((const float4*)h)[idx];
    red4(g + (size_t)batch[node] * 128 + qq * 4, v);
}
__global__ void out_kernel(const float* __restrict__ gf, const float* __restrict__ oW,
                           const float* __restrict__ ob, float* __restrict__ out) {
    int gidx = blockIdx.x * 8 + (threadIdx.x >> 5);
    int lane = threadIdx.x & 31;
    if (gidx >= NG) return;
    float s = 0.f;
#pragma unroll
    for (int k = lane; k < 128; k += 32) s += gf[gidx * 128 + k] * oW[k];
#pragma unroll
    for (int o = 16; o; o >>= 1) s += __shfl_down_sync(0xffffffffu, s, o);
    if (lane == 0) out[gidx] = s + ob[0];
}

// ---------------- launch ----------------
extern "C" void kernel_launch(void* const* d_in, const int* in_sizes, int n_in,
                              void* d_out, int out_size) {
    (void)in_sizes; (void)n_in; (void)out_size;
    const float* x   = (const float*)d_in[0];
    const int*   ei  = (const int*)d_in[1];
    const float* ea  = (const float*)d_in[2];
    const int*   bat = (const int*)d_in[3];
    const float* Wf  = (const float*)d_in[4];
    const float* bf  = (const float*)d_in[5];
    const float* Ws  = (const float*)d_in[6];
    const float* bs  = (const float*)d_in[7];
    const float* m1W0 = (const float*)d_in[8],  *m1b0 = (const float*)d_in[9];
    const float* m1W1 = (const float*)d_in[10], *m1b1 = (const float*)d_in[11];
    const float* m1Wp = (const float*)d_in[12], *m1bp = (const float*)d_in[13];
    const float* m2W0 = (const float*)d_in[14], *m2b0 = (const float*)d_in[15];
    const float* m2W1 = (const float*)d_in[16], *m2b1 = (const float*)d_in[17];
    const float* m2Wp = (const float*)d_in[18], *m2bp = (const float*)d_in[19];
    const float* oW   = (const float*)d_in[20], *ob   = (const float*)d_in[21];
    float* out = (float*)d_out;

    float *pH0, *pH1, *pP, *pW, *pB, *pPool, *pT0g, *pT1g, *pGf;
    cudaGetSymbolAddress((void**)&pH0,  g_h0);
    cudaGetSymbolAddress((void**)&pH1,  g_h1);
    cudaGetSymbolAddress((void**)&pP,   g_P);
    cudaGetSymbolAddress((void**)&pW,   g_Wcat);
    cudaGetSymbolAddress((void**)&pB,   g_bcat);
    cudaGetSymbolAddress((void**)&pPool, g_pool);
    cudaGetSymbolAddress((void**)&pT0g, g_t0g);
    cudaGetSymbolAddress((void**)&pT1g, g_t1g);
    cudaGetSymbolAddress((void**)&pGf,  g_gfin);

    const int EDGE_SMEM = 65536 + 32768;   // 96KB
    cudaFuncSetAttribute(edge_kernel, cudaFuncAttributeMaxDynamicSharedMemorySize, EDGE_SMEM);

    const int MB = (NN + 127) / 128;   // 391
    const int EGRID = 304;             // 2 per SM on 152 SMs

    // --- CGConv layer 0 ---
    pack_wcat<<<(512 * 128 + 255) / 256, 256>>>(Wf, Ws, bf, bs, pW, pB, 0);
    sgemm_bt<<<dim3(4, MB), 256>>>(x, pW, pB, nullptr, pP, NN, 512, 128, 0);
    copy_kernel<<<(NN * 32 + 255) / 256, 256>>>(x, pH0, NN * 32);
    edge_kernel<<<EGRID, 256, EDGE_SMEM>>>(pP, ei, ea, Wf, Ws, 0, pH0);

    // --- CGConv layer 1 ---
    pack_wcat<<<(512 * 128 + 255) / 256, 256>>>(Wf, Ws, bf, bs, pW, pB, 1);
    sgemm_bt<<<dim3(4, MB), 256>>>(pH0, pW, pB, nullptr, pP, NN, 512, 128, 0);
    copy_kernel<<<(NN * 32 + 255) / 256, 256>>>(pH0, pH1, NN * 32);
    edge_kernel<<<EGRID, 256, EDGE_SMEM>>>(pP, ei, ea, Wf, Ws, 1, pH1);

    // --- node MLP (residual) ---
    float* t0 = pP;
    float* t1 = pP + (size_t)NN * 256;
    sgemm_bt<<<dim3(2, MB), 256>>>(pH1, m1W0, m1b0, nullptr, t0, NN, 256, 128, 1);
    sgemm_bt<<<dim3(2, MB), 256>>>(t0, m1W1, m1b1, nullptr, t1, NN, 256, 256, 1);
    sgemm_bt<<<dim3(1, MB), 256>>>(t1, m1Wp, m1bp, pH1, pH0, NN, 128, 256, 0);

    // --- global add pool ---
    zero_kernel<<<(NG * 128 + 255) / 256, 256>>>(pPool, NG * 128);
    pool_kernel<<<(NN * 32 + 255) / 256, 256>>>(pH0, bat, pPool);

    // --- graph MLP (residual) + head ---
    sgemm_bt<<<dim3(2, 4), 256>>>(pPool, m2W0, m2b0, nullptr, pT0g, NG, 256, 128, 1);
    sgemm_bt<<<dim3(2, 4), 256>>>(pT0g, m2W1, m2b1, nullptr, pT1g, NG, 256, 256, 1);
    sgemm_bt<<<dim3(1, 4), 256>>>(pT1g, m2Wp, m2bp, pPool, pGf, NG, 128, 256, 0);
    out_kernel<<<64, 256>>>(pGf, oW, ob, out);
}

// round 8
// speedup vs baseline: 1.3737x; 1.1198x over previous
#include <cuda_runtime.h>
#include <cstdint>

#define NN 50000
#define NE 800000
#define NG 512

// ---------------- device scratch (static, no runtime alloc) ----------------
__device__ float g_h0[NN * 128];
__device__ float g_h1[NN * 128];
__device__ float g_P [NN * 512];
__device__ float g_Wcat[512 * 128];
__device__ float g_bcat[512];
__device__ float g_pool[NG * 128];
__device__ float g_t0g[NG * 256];
__device__ float g_t1g[NG * 256];
__device__ float g_gfin[NG * 128];

// ---------------- f32x2 helpers ----------------
typedef unsigned long long u64;
__device__ __forceinline__ u64 pk2(float lo, float hi) {
    u64 r; asm("mov.b64 %0,{%1,%2};" : "=l"(r) : "f"(lo), "f"(hi)); return r;
}
__device__ __forceinline__ float2 up2(u64 v) {
    float2 r; asm("mov.b64 {%0,%1},%2;" : "=f"(r.x), "=f"(r.y) : "l"(v)); return r;
}
__device__ __forceinline__ u64 ffma2(u64 a, u64 b, u64 c) {
    u64 d; asm("fma.rn.f32x2 %0,%1,%2,%3;" : "=l"(d) : "l"(a), "l"(b), "l"(c)); return d;
}
union F4U { float4 f4; u64 u[2]; float f[4]; };

__device__ __forceinline__ void red4(float* addr, float4 v) {
    asm volatile("red.global.add.v4.f32 [%0], {%1,%2,%3,%4};"
                 :: "l"(addr), "f"(v.x), "f"(v.y), "f"(v.z), "f"(v.w) : "memory");
}
__device__ __forceinline__ void red2(float* addr, float2 v) {
    asm volatile("red.global.add.v2.f32 [%0], {%1,%2};"
                 :: "l"(addr), "f"(v.x), "f"(v.y) : "memory");
}
__device__ __forceinline__ void cpasync16(unsigned saddr, const void* gaddr) {
    asm volatile("cp.async.cg.shared.global [%0], [%1], 16;" :: "r"(saddr), "l"(gaddr));
}
__device__ __forceinline__ void cpcommit() { asm volatile("cp.async.commit_group;"); }
__device__ __forceinline__ void cpwait0()  { asm volatile("cp.async.wait_group 0;"); }

__device__ __forceinline__ float sigm(float x) { return 1.f / (1.f + __expf(-x)); }
__device__ __forceinline__ float softp(float x) {
    return fmaxf(x, 0.f) + __logf(1.f + __expf(-fabsf(x)));
}
__device__ __forceinline__ unsigned f2tf(float x) {
    unsigned r; asm("cvt.rna.tf32.f32 %0, %1;" : "=r"(r) : "f"(x)); return r;
}
__device__ __forceinline__ void mma_tf32_16n8k8(float* c, unsigned a0, unsigned a1,
                                                unsigned a2, unsigned a3,
                                                unsigned b0, unsigned b1) {
    asm volatile(
        "mma.sync.aligned.m16n8k8.row.col.f32.tf32.tf32.f32 "
        "{%0,%1,%2,%3}, {%4,%5,%6,%7}, {%8,%9}, {%0,%1,%2,%3};"
        : "+f"(c[0]), "+f"(c[1]), "+f"(c[2]), "+f"(c[3])
        : "r"(a0), "r"(a1), "r"(a2), "r"(a3), "r"(b0), "r"(b1));
}

// ---------------- pack concatenated projection weights ----------------
__global__ void pack_wcat(const float* __restrict__ Wf, const float* __restrict__ Ws,
                          const float* __restrict__ bf, const float* __restrict__ bs,
                          float* __restrict__ Wcat, float* __restrict__ bcat, int layer) {
    int idx = blockIdx.x * blockDim.x + threadIdx.x;
    if (idx < 512) {
        float b = 0.f;
        if (idx < 128) b = bf[layer * 128 + idx];
        else if (idx < 256) b = bs[layer * 128 + idx - 128];
        bcat[idx] = b;
    }
    if (idx >= 512 * 128) return;
    int n = idx >> 7, k = idx & 127;
    const float* W; int o, koff;
    if      (n < 128) { W = Wf; o = n;       koff = 0;   }
    else if (n < 256) { W = Ws; o = n - 128; koff = 0;   }
    else if (n < 384) { W = Wf; o = n - 256; koff = 128; }
    else              { W = Ws; o = n - 384; koff = 128; }
    Wcat[idx] = W[((size_t)(layer * 128 + o)) * 320 + koff + k];
}

// ---------------- SGEMM (R1, BK=8) ----------------
__global__ void __launch_bounds__(256) sgemm_bt(
    const float* __restrict__ A, const float* __restrict__ B,
    const float* __restrict__ bias, const float* __restrict__ res,
    float* __restrict__ C, int M, int N, int K, int relu) {
    __shared__ float As[8][128];
    __shared__ float Bs[8][128];
    int tid = threadIdx.x;
    int m0 = blockIdx.y * 128;
    int n0 = blockIdx.x * 128;
    int tx = tid & 15, ty = tid >> 4;
    int lr = tid >> 1;
    int lk = (tid & 1) * 4;

    u64 acc[8][4];
#pragma unroll
    for (int i = 0; i < 8; i++)
#pragma unroll
        for (int j = 0; j < 4; j++) acc[i][j] = 0ull;

    for (int k0 = 0; k0 < K; k0 += 8) {
        float4 av = make_float4(0.f, 0.f, 0.f, 0.f);
        int arow = m0 + lr;
        if (arow < M) av = *(const float4*)(A + (size_t)arow * K + k0 + lk);
        As[lk + 0][lr] = av.x; As[lk + 1][lr] = av.y;
        As[lk + 2][lr] = av.z; As[lk + 3][lr] = av.w;
        float4 bv = *(const float4*)(B + (size_t)(n0 + lr) * K + k0 + lk);
        Bs[lk + 0][lr] = bv.x; Bs[lk + 1][lr] = bv.y;
        Bs[lk + 2][lr] = bv.z; Bs[lk + 3][lr] = bv.w;
        __syncthreads();
#pragma unroll
        for (int k = 0; k < 8; k++) {
            F4U b0, b1;
            b0.f4 = *(const float4*)&Bs[k][tx * 8];
            b1.f4 = *(const float4*)&Bs[k][tx * 8 + 4];
            float4 a0 = *(const float4*)&As[k][ty * 8];
            float4 a1 = *(const float4*)&As[k][ty * 8 + 4];
            float a[8] = {a0.x, a0.y, a0.z, a0.w, a1.x, a1.y, a1.z, a1.w};
#pragma unroll
            for (int i = 0; i < 8; i++) {
                u64 ai = pk2(a[i], a[i]);
                acc[i][0] = ffma2(ai, b0.u[0], acc[i][0]);
                acc[i][1] = ffma2(ai, b0.u[1], acc[i][1]);
                acc[i][2] = ffma2(ai, b1.u[0], acc[i][2]);
                acc[i][3] = ffma2(ai, b1.u[1], acc[i][3]);
            }
        }
        __syncthreads();
    }

#pragma unroll
    for (int i = 0; i < 8; i++) {
        int row = m0 + ty * 8 + i;
        if (row >= M) continue;
        int n = n0 + tx * 8;
        float o[8];
#pragma unroll
        for (int j2 = 0; j2 < 4; j2++) {
            float2 v = up2(acc[i][j2]);
            o[2 * j2] = v.x; o[2 * j2 + 1] = v.y;
        }
#pragma unroll
        for (int j = 0; j < 8; j++) {
            float v = o[j] + bias[n + j];
            if (res) v += res[(size_t)row * N + n + j];
            if (relu) v = fmaxf(v, 0.f);
            o[j] = v;
        }
        *(float4*)(C + (size_t)row * N + n)     = make_float4(o[0], o[1], o[2], o[3]);
        *(float4*)(C + (size_t)row * N + n + 4) = make_float4(o[4], o[5], o[6], o[7]);
    }
}

// ---------------- edge kernel v6: HMMA tf32 (mma.sync m16n8k8) ----------------
// Group = 16 edges. Warp w owns output cols [16w,16w+16) for BOTH f and s.
// B (weights) live in 64 persistent tf32 register fragments per thread.
// Accumulator layout pairs f-col j and s-col j in the SAME thread -> direct epilogue.
__global__ void __launch_bounds__(256, 2) edge_hmma_kernel(
    const float* __restrict__ Pall, const int* __restrict__ ei,
    const float* __restrict__ ea, const float* __restrict__ Wf,
    const float* __restrict__ Ws, int layer, float* __restrict__ hout) {
    __shared__ float sEa[2][16][68];
    __shared__ int sIdx[2][32];

    int tid = threadIdx.x, w = tid >> 5, lane = tid & 31;
    int q = lane & 3, r0 = lane >> 2;

    // ---- persistent B fragments: 4 n-tiles (f0,f1,s0,s1) x 8 k-steps x 2 regs ----
    unsigned bfr[4][8][2];
#pragma unroll
    for (int nt = 0; nt < 4; nt++) {
        int j = w * 16 + (nt & 1) * 8 + r0;   // output col 0..127
        const float* Wp = ((nt < 2) ? Wf : Ws) + (size_t)(layer * 128 + j) * 320 + 256;
#pragma unroll
        for (int ks = 0; ks < 8; ks++) {
            bfr[nt][ks][0] = f2tf(__ldg(Wp + ks * 8 + q));
            bfr[nt][ks][1] = f2tf(__ldg(Wp + ks * 8 + q + 4));
        }
    }

    const int NT = NE / 16;   // 50000 groups
    int nbs = gridDim.x;
    int tile = blockIdx.x;

    // stage: cp.async EA[16][64] + idx[32] into buffer bb
    auto stage = [&](int t, int bb) {
        int e0 = t << 4;
        int row = tid >> 4, ch = tid & 15;
        unsigned daddr = (unsigned)__cvta_generic_to_shared(&sEa[bb][row][0]) + ch * 16;
        cpasync16(daddr, ea + (size_t)(e0 + row) * 64 + ch * 4);
        if (tid < 32) sIdx[bb][tid] = ei[(tid < 16 ? 0 : NE) + e0 + (tid & 15)];
    };

    if (tile < NT) stage(tile, 0);
    cpcommit();

    int buf = 0;
    for (; tile < NT; tile += nbs) {
        cpwait0();
        __syncthreads();                 // data(tile) visible; prev compute done
        int nxt = tile + nbs;
        if (nxt < NT) stage(nxt, buf ^ 1);
        cpcommit();

        // ---- tensor-core GEMM: 16 edges x 64 cols (this warp) ----
        float acc[4][4];
#pragma unroll
        for (int nt = 0; nt < 4; nt++)
#pragma unroll
            for (int j = 0; j < 4; j++) acc[nt][j] = 0.f;

#pragma unroll
        for (int ks = 0; ks < 8; ks++) {
            unsigned a0 = f2tf(sEa[buf][r0][ks * 8 + q]);
            unsigned a1 = f2tf(sEa[buf][r0 + 8][ks * 8 + q]);
            unsigned a2 = f2tf(sEa[buf][r0][ks * 8 + q + 4]);
            unsigned a3 = f2tf(sEa[buf][r0 + 8][ks * 8 + q + 4]);
#pragma unroll
            for (int nt = 0; nt < 4; nt++)
                mma_tf32_16n8k8(acc[nt], a0, a1, a2, a3, bfr[nt][ks][0], bfr[nt][ks][1]);
        }

        // ---- epilogue: gather P, activate, scatter ----
#pragma unroll
        for (int nt = 0; nt < 2; nt++) {
#pragma unroll
            for (int half = 0; half < 2; half++) {
                int row = r0 + half * 8;
                int sN = sIdx[buf][row], dN = sIdx[buf][16 + row];
                int j = w * 16 + nt * 8 + 2 * q;
                const float* pd = Pall + (size_t)dN * 512;
                const float* ps = Pall + (size_t)sN * 512;
                float2 fd  = *(const float2*)(pd + j);
                float2 sd  = *(const float2*)(pd + 128 + j);
                float2 fs2 = *(const float2*)(ps + 256 + j);
                float2 ss2 = *(const float2*)(ps + 384 + j);
                float fa = acc[nt][half * 2 + 0] + fd.x + fs2.x;
                float fb = acc[nt][half * 2 + 1] + fd.y + fs2.y;
                float sa = acc[nt + 2][half * 2 + 0] + sd.x + ss2.x;
                float sb = acc[nt + 2][half * 2 + 1] + sd.y + ss2.y;
                float2 m = make_float2(sigm(fa) * softp(sa), sigm(fb) * softp(sb));
                red2(hout + (size_t)dN * 128 + j, m);
            }
        }
        buf ^= 1;
    }
}

// ---------------- small utility kernels ----------------
__global__ void copy_kernel(const float* __restrict__ a, float* __restrict__ b, int n4) {
    int i = blockIdx.x * blockDim.x + threadIdx.x;
    if (i < n4) ((float4*)b)[i] = ((const float4*)a)[i];
}
__global__ void zero_kernel(float* __restrict__ p, int n) {
    int i = blockIdx.x * blockDim.x + threadIdx.x;
    if (i < n) p[i] = 0.f;
}
__global__ void pool_kernel(const float* __restrict__ h, const int* __restrict__ batch,
                            float* __restrict__ g) {
    int idx = blockIdx.x * blockDim.x + threadIdx.x;
    if (idx >= NN * 32) return;
    int node = idx >> 5, qq = idx & 31;
    float4 v = ((const float4*)h)[idx];
    red4(g + (size_t)batch[node] * 128 + qq * 4, v);
}
__global__ void out_kernel(const float* __restrict__ gf, const float* __restrict__ oW,
                           const float* __restrict__ ob, float* __restrict__ out) {
    int gidx = blockIdx.x * 8 + (threadIdx.x >> 5);
    int lane = threadIdx.x & 31;
    if (gidx >= NG) return;
    float s = 0.f;
#pragma unroll
    for (int k = lane; k < 128; k += 32) s += gf[gidx * 128 + k] * oW[k];
#pragma unroll
    for (int o = 16; o; o >>= 1) s += __shfl_down_sync(0xffffffffu, s, o);
    if (lane == 0) out[gidx] = s + ob[0];
}

// ---------------- launch ----------------
extern "C" void kernel_launch(void* const* d_in, const int* in_sizes, int n_in,
                              void* d_out, int out_size) {
    (void)in_sizes; (void)n_in; (void)out_size;
    const float* x   = (const float*)d_in[0];
    const int*   ei  = (const int*)d_in[1];
    const float* ea  = (const float*)d_in[2];
    const int*   bat = (const int*)d_in[3];
    const float* Wf  = (const float*)d_in[4];
    const float* bf  = (const float*)d_in[5];
    const float* Ws  = (const float*)d_in[6];
    const float* bs  = (const float*)d_in[7];
    const float* m1W0 = (const float*)d_in[8],  *m1b0 = (const float*)d_in[9];
    const float* m1W1 = (const float*)d_in[10], *m1b1 = (const float*)d_in[11];
    const float* m1Wp = (const float*)d_in[12], *m1bp = (const float*)d_in[13];
    const float* m2W0 = (const float*)d_in[14], *m2b0 = (const float*)d_in[15];
    const float* m2W1 = (const float*)d_in[16], *m2b1 = (const float*)d_in[17];
    const float* m2Wp = (const float*)d_in[18], *m2bp = (const float*)d_in[19];
    const float* oW   = (const float*)d_in[20], *ob   = (const float*)d_in[21];
    float* out = (float*)d_out;

    float *pH0, *pH1, *pP, *pW, *pB, *pPool, *pT0g, *pT1g, *pGf;
    cudaGetSymbolAddress((void**)&pH0,  g_h0);
    cudaGetSymbolAddress((void**)&pH1,  g_h1);
    cudaGetSymbolAddress((void**)&pP,   g_P);
    cudaGetSymbolAddress((void**)&pW,   g_Wcat);
    cudaGetSymbolAddress((void**)&pB,   g_bcat);
    cudaGetSymbolAddress((void**)&pPool, g_pool);
    cudaGetSymbolAddress((void**)&pT0g, g_t0g);
    cudaGetSymbolAddress((void**)&pT1g, g_t1g);
    cudaGetSymbolAddress((void**)&pGf,  g_gfin);

    const int MB = (NN + 127) / 128;   // 391
    const int EGRID = 304;             // 2 per SM on 152 SMs

    // --- CGConv layer 0 ---
    pack_wcat<<<(512 * 128 + 255) / 256, 256>>>(Wf, Ws, bf, bs, pW, pB, 0);
    sgemm_bt<<<dim3(4, MB), 256>>>(x, pW, pB, nullptr, pP, NN, 512, 128, 0);
    copy_kernel<<<(NN * 32 + 255) / 256, 256>>>(x, pH0, NN * 32);
    edge_hmma_kernel<<<EGRID, 256>>>(pP, ei, ea, Wf, Ws, 0, pH0);

    // --- CGConv layer 1 ---
    pack_wcat<<<(512 * 128 + 255) / 256, 256>>>(Wf, Ws, bf, bs, pW, pB, 1);
    sgemm_bt<<<dim3(4, MB), 256>>>(pH0, pW, pB, nullptr, pP, NN, 512, 128, 0);
    copy_kernel<<<(NN * 32 + 255) / 256, 256>>>(pH0, pH1, NN * 32);
    edge_hmma_kernel<<<EGRID, 256>>>(pP, ei, ea, Wf, Ws, 1, pH1);

    // --- node MLP (residual) ---
    float* t0 = pP;
    float* t1 = pP + (size_t)NN * 256;
    sgemm_bt<<<dim3(2, MB), 256>>>(pH1, m1W0, m1b0, nullptr, t0, NN, 256, 128, 1);
    sgemm_bt<<<dim3(2, MB), 256>>>(t0, m1W1, m1b1, nullptr, t1, NN, 256, 256, 1);
    sgemm_bt<<<dim3(1, MB), 256>>>(t1, m1Wp, m1bp, pH1, pH0, NN, 128, 256, 0);

    // --- global add pool ---
    zero_kernel<<<(NG * 128 + 255) / 256, 256>>>(pPool, NG * 128);
    pool_kernel<<<(NN * 32 + 255) / 256, 256>>>(pH0, bat, pPool);

    // --- graph MLP (residual) + head ---
    sgemm_bt<<<dim3(2, 4), 256>>>(pPool, m2W0, m2b0, nullptr, pT0g, NG, 256, 128, 1);
    sgemm_bt<<<dim3(2, 4), 256>>>(pT0g, m2W1, m2b1, nullptr, pT1g, NG, 256, 256, 1);
    sgemm_bt<<<dim3(1, 4), 256>>>(pT1g, m2Wp, m2bp, pPool, pGf, NG, 128, 256, 0);
    out_kernel<<<64, 256>>>(pGf, oW, ob, out);
}

// round 10
// speedup vs baseline: 1.8626x; 1.3559x over previous
#include <cuda_runtime.h>
#include <cstdint>

#define NN 50000
#define NE 800000
#define NG 512

// ---------------- device scratch (static, no runtime alloc) ----------------
__device__ float g_h0[NN * 128];
__device__ float g_h1[NN * 128];
__device__ float g_P [NN * 512];
__device__ float g_Wcat[512 * 128];
__device__ float g_bcat[512];
__device__ float g_pool[NG * 128];
__device__ float g_t0g[NG * 256];
__device__ float g_t1g[NG * 256];
__device__ float g_gfin[NG * 128];

// ---------------- helpers ----------------
typedef unsigned long long u64;
__device__ __forceinline__ u64 pk2(float lo, float hi) {
    u64 r; asm("mov.b64 %0,{%1,%2};" : "=l"(r) : "f"(lo), "f"(hi)); return r;
}
__device__ __forceinline__ float2 up2(u64 v) {
    float2 r; asm("mov.b64 {%0,%1},%2;" : "=f"(r.x), "=f"(r.y) : "l"(v)); return r;
}
__device__ __forceinline__ u64 ffma2(u64 a, u64 b, u64 c) {
    u64 d; asm("fma.rn.f32x2 %0,%1,%2,%3;" : "=l"(d) : "l"(a), "l"(b), "l"(c)); return d;
}
union F4U { float4 f4; u64 u[2]; float f[4]; };

__device__ __forceinline__ void red4(float* addr, float4 v) {
    asm volatile("red.global.add.v4.f32 [%0], {%1,%2,%3,%4};"
                 :: "l"(addr), "f"(v.x), "f"(v.y), "f"(v.z), "f"(v.w) : "memory");
}
__device__ __forceinline__ void red2(float* addr, float2 v) {
    asm volatile("red.global.add.v2.f32 [%0], {%1,%2};"
                 :: "l"(addr), "f"(v.x), "f"(v.y) : "memory");
}
__device__ __forceinline__ void cpasync16(unsigned saddr, const void* gaddr) {
    asm volatile("cp.async.cg.shared.global [%0], [%1], 16;" :: "r"(saddr), "l"(gaddr));
}
__device__ __forceinline__ void cpcommit() { asm volatile("cp.async.commit_group;"); }
__device__ __forceinline__ void cpwait0()  { asm volatile("cp.async.wait_group 0;"); }

__device__ __forceinline__ float sigm(float x) { return 1.f / (1.f + __expf(-x)); }
__device__ __forceinline__ float softp(float x) {
    return fmaxf(x, 0.f) + __logf(1.f + __expf(-fabsf(x)));
}
__device__ __forceinline__ unsigned f2tf(float x) {
    unsigned r; asm("cvt.rna.tf32.f32 %0, %1;" : "=r"(r) : "f"(x)); return r;
}
__device__ __forceinline__ void mma_tf32_16n8k8(float* c, unsigned a0, unsigned a1,
                                                unsigned a2, unsigned a3,
                                                unsigned b0, unsigned b1) {
    asm volatile(
        "mma.sync.aligned.m16n8k8.row.col.f32.tf32.tf32.f32 "
        "{%0,%1,%2,%3}, {%4,%5,%6,%7}, {%8,%9}, {%0,%1,%2,%3};"
        : "+f"(c[0]), "+f"(c[1]), "+f"(c[2]), "+f"(c[3])
        : "r"(a0), "r"(a1), "r"(a2), "r"(a3), "r"(b0), "r"(b1));
}

// ---------------- pack concatenated projection weights ----------------
__global__ void pack_wcat(const float* __restrict__ Wf, const float* __restrict__ Ws,
                          const float* __restrict__ bf, const float* __restrict__ bs,
                          float* __restrict__ Wcat, float* __restrict__ bcat, int layer) {
    int idx = blockIdx.x * blockDim.x + threadIdx.x;
    if (idx < 512) {
        float b = 0.f;
        if (idx < 128) b = bf[layer * 128 + idx];
        else if (idx < 256) b = bs[layer * 128 + idx - 128];
        bcat[idx] = b;
    }
    if (idx >= 512 * 128) return;
    int n = idx >> 7, k = idx & 127;
    const float* W; int o, koff;
    if      (n < 128) { W = Wf; o = n;       koff = 0;   }
    else if (n < 256) { W = Ws; o = n - 128; koff = 0;   }
    else if (n < 384) { W = Wf; o = n - 256; koff = 128; }
    else              { W = Ws; o = n - 384; koff = 128; }
    Wcat[idx] = W[((size_t)(layer * 128 + o)) * 320 + koff + k];
}

// ---------------- HMMA tf32 GEMM: C[M,N] = act(A[M,K] @ B[N,K]^T + bias (+res)) ----------------
// CTA 128x128, 8 warps (2m x 4n), warp tile 64x32 (4x4 m16n8k8), BK=32, cp.async double buffer.
#define GLDS 36
#define HMMA_SMEM (2 * 2 * 128 * GLDS * 4)   // 73728 bytes

__global__ void __launch_bounds__(256) hmma_gemm(
    const float* __restrict__ A, const float* __restrict__ B,
    const float* __restrict__ bias, const float* __restrict__ res,
    float* __restrict__ C, int M, int N, int K, int relu) {
    extern __shared__ float sm[];
    float* sA = sm;                      // [2][128][GLDS]
    float* sB = sm + 2 * 128 * GLDS;     // [2][128][GLDS]
    unsigned saA = (unsigned)__cvta_generic_to_shared(sA);
    unsigned saB = (unsigned)__cvta_generic_to_shared(sB);

    int tid = threadIdx.x, wid = tid >> 5, lane = tid & 31;
    int warp_m = wid >> 2, warp_n = wid & 3;
    int r0 = lane >> 2, q = lane & 3;
    int m0 = blockIdx.y * 128, n0 = blockIdx.x * 128;

    // stage BK=32 slice at k0 into buffer bb
    auto stage = [&](int k0, int bb) {
#pragma unroll
        for (int t = 0; t < 4; t++) {
            int idx = tid + t * 256;
            int row = idx >> 3, c4 = idx & 7;
            int ar = m0 + row;
            if (ar < M)
                cpasync16(saA + (unsigned)(((bb * 128 + row) * GLDS + c4 * 4) * 4),
                          A + (size_t)ar * K + k0 + c4 * 4);
            cpasync16(saB + (unsigned)(((bb * 128 + row) * GLDS + c4 * 4) * 4),
                      B + (size_t)(n0 + row) * K + k0 + c4 * 4);
        }
    };

    float acc[4][4][4];
#pragma unroll
    for (int mt = 0; mt < 4; mt++)
#pragma unroll
        for (int nt = 0; nt < 4; nt++)
#pragma unroll
            for (int j = 0; j < 4; j++) acc[mt][nt][j] = 0.f;

    int nst = K >> 5;
    stage(0, 0); cpcommit();
    for (int s = 0; s < nst; s++) {
        cpwait0();
        __syncthreads();
        if (s + 1 < nst) { stage((s + 1) << 5, (s + 1) & 1); cpcommit(); }
        int bb = s & 1;
        const float* bA = sA + bb * 128 * GLDS;
        const float* bBp = sB + bb * 128 * GLDS;
#pragma unroll
        for (int ks = 0; ks < 4; ks++) {
            int k = ks * 8;
            unsigned af[4][4], bf4[4][2];
#pragma unroll
            for (int mt = 0; mt < 4; mt++) {
                const float* ap = bA + (warp_m * 64 + mt * 16 + r0) * GLDS + k + q;
                af[mt][0] = f2tf(ap[0]);
                af[mt][1] = f2tf(ap[8 * GLDS]);
                af[mt][2] = f2tf(ap[4]);
                af[mt][3] = f2tf(ap[8 * GLDS + 4]);
            }
#pragma unroll
            for (int nt = 0; nt < 4; nt++) {
                const float* bp = bBp + (warp_n * 32 + nt * 8 + r0) * GLDS + k + q;
                bf4[nt][0] = f2tf(bp[0]);
                bf4[nt][1] = f2tf(bp[4]);
            }
#pragma unroll
            for (int mt = 0; mt < 4; mt++)
#pragma unroll
                for (int nt = 0; nt < 4; nt++)
                    mma_tf32_16n8k8(acc[mt][nt], af[mt][0], af[mt][1], af[mt][2], af[mt][3],
                                    bf4[nt][0], bf4[nt][1]);
        }
        __syncthreads();
    }

    // epilogue
#pragma unroll
    for (int mt = 0; mt < 4; mt++) {
#pragma unroll
        for (int half = 0; half < 2; half++) {
            int row = m0 + warp_m * 64 + mt * 16 + r0 + half * 8;
            if (row >= M) continue;
#pragma unroll
            for (int nt = 0; nt < 4; nt++) {
                int col = n0 + warp_n * 32 + nt * 8 + 2 * q;
                float v0 = acc[mt][nt][half * 2 + 0] + bias[col];
                float v1 = acc[mt][nt][half * 2 + 1] + bias[col + 1];
                if (res) {
                    float2 rv = *(const float2*)(res + (size_t)row * N + col);
                    v0 += rv.x; v1 += rv.y;
                }
                if (relu) { v0 = fmaxf(v0, 0.f); v1 = fmaxf(v1, 0.f); }
                *(float2*)(C + (size_t)row * N + col) = make_float2(v0, v1);
            }
        }
    }
}

// ---------------- SGEMM fp32 (graph-level, small) ----------------
__global__ void __launch_bounds__(256) sgemm_bt(
    const float* __restrict__ A, const float* __restrict__ B,
    const float* __restrict__ bias, const float* __restrict__ res,
    float* __restrict__ C, int M, int N, int K, int relu) {
    __shared__ float As[8][128];
    __shared__ float Bs[8][128];
    int tid = threadIdx.x;
    int m0 = blockIdx.y * 128;
    int n0 = blockIdx.x * 128;
    int tx = tid & 15, ty = tid >> 4;
    int lr = tid >> 1;
    int lk = (tid & 1) * 4;

    u64 acc[8][4];
#pragma unroll
    for (int i = 0; i < 8; i++)
#pragma unroll
        for (int j = 0; j < 4; j++) acc[i][j] = 0ull;

    for (int k0 = 0; k0 < K; k0 += 8) {
        float4 av = make_float4(0.f, 0.f, 0.f, 0.f);
        int arow = m0 + lr;
        if (arow < M) av = *(const float4*)(A + (size_t)arow * K + k0 + lk);
        As[lk + 0][lr] = av.x; As[lk + 1][lr] = av.y;
        As[lk + 2][lr] = av.z; As[lk + 3][lr] = av.w;
        float4 bv = *(const float4*)(B + (size_t)(n0 + lr) * K + k0 + lk);
        Bs[lk + 0][lr] = bv.x; Bs[lk + 1][lr] = bv.y;
        Bs[lk + 2][lr] = bv.z; Bs[lk + 3][lr] = bv.w;
        __syncthreads();
#pragma unroll
        for (int k = 0; k < 8; k++) {
            F4U b0, b1;
            b0.f4 = *(const float4*)&Bs[k][tx * 8];
            b1.f4 = *(const float4*)&Bs[k][tx * 8 + 4];
            float4 a0 = *(const float4*)&As[k][ty * 8];
            float4 a1 = *(const float4*)&As[k][ty * 8 + 4];
            float a[8] = {a0.x, a0.y, a0.z, a0.w, a1.x, a1.y, a1.z, a1.w};
#pragma unroll
            for (int i = 0; i < 8; i++) {
                u64 ai = pk2(a[i], a[i]);
                acc[i][0] = ffma2(ai, b0.u[0], acc[i][0]);
                acc[i][1] = ffma2(ai, b0.u[1], acc[i][1]);
                acc[i][2] = ffma2(ai, b1.u[0], acc[i][2]);
                acc[i][3] = ffma2(ai, b1.u[1], acc[i][3]);
            }
        }
        __syncthreads();
    }

#pragma unroll
    for (int i = 0; i < 8; i++) {
        int row = m0 + ty * 8 + i;
        if (row >= M) continue;
        int n = n0 + tx * 8;
        float o[8];
#pragma unroll
        for (int j2 = 0; j2 < 4; j2++) {
            float2 v = up2(acc[i][j2]);
            o[2 * j2] = v.x; o[2 * j2 + 1] = v.y;
        }
#pragma unroll
        for (int j = 0; j < 8; j++) {
            float v = o[j] + bias[n + j];
            if (res) v += res[(size_t)row * N + n + j];
            if (relu) v = fmaxf(v, 0.f);
            o[j] = v;
        }
        *(float4*)(C + (size_t)row * N + n)     = make_float4(o[0], o[1], o[2], o[3]);
        *(float4*)(C + (size_t)row * N + n + 4) = make_float4(o[4], o[5], o[6], o[7]);
    }
}

// ---------------- edge kernel v6: HMMA tf32 (unchanged from R8 win) ----------------
__global__ void __launch_bounds__(256, 2) edge_hmma_kernel(
    const float* __restrict__ Pall, const int* __restrict__ ei,
    const float* __restrict__ ea, const float* __restrict__ Wf,
    const float* __restrict__ Ws, int layer, float* __restrict__ hout) {
    __shared__ float sEa[2][16][68];
    __shared__ int sIdx[2][32];

    int tid = threadIdx.x, w = tid >> 5, lane = tid & 31;
    int q = lane & 3, r0 = lane >> 2;

    unsigned bfr[4][8][2];
#pragma unroll
    for (int nt = 0; nt < 4; nt++) {
        int j = w * 16 + (nt & 1) * 8 + r0;
        const float* Wp = ((nt < 2) ? Wf : Ws) + (size_t)(layer * 128 + j) * 320 + 256;
#pragma unroll
        for (int ks = 0; ks < 8; ks++) {
            bfr[nt][ks][0] = f2tf(__ldg(Wp + ks * 8 + q));
            bfr[nt][ks][1] = f2tf(__ldg(Wp + ks * 8 + q + 4));
        }
    }

    const int NT = NE / 16;
    int nbs = gridDim.x;
    int tile = blockIdx.x;

    auto stage = [&](int t, int bb) {
        int e0 = t << 4;
        int row = tid >> 4, ch = tid & 15;
        unsigned daddr = (unsigned)__cvta_generic_to_shared(&sEa[bb][row][0]) + ch * 16;
        cpasync16(daddr, ea + (size_t)(e0 + row) * 64 + ch * 4);
        if (tid < 32) sIdx[bb][tid] = ei[(tid < 16 ? 0 : NE) + e0 + (tid & 15)];
    };

    if (tile < NT) stage(tile, 0);
    cpcommit();

    int buf = 0;
    for (; tile < NT; tile += nbs) {
        cpwait0();
        __syncthreads();
        int nxt = tile + nbs;
        if (nxt < NT) stage(nxt, buf ^ 1);
        cpcommit();

        float acc[4][4];
#pragma unroll
        for (int nt = 0; nt < 4; nt++)
#pragma unroll
            for (int j = 0; j < 4; j++) acc[nt][j] = 0.f;

#pragma unroll
        for (int ks = 0; ks < 8; ks++) {
            unsigned a0 = f2tf(sEa[buf][r0][ks * 8 + q]);
            unsigned a1 = f2tf(sEa[buf][r0 + 8][ks * 8 + q]);
            unsigned a2 = f2tf(sEa[buf][r0][ks * 8 + q + 4]);
            unsigned a3 = f2tf(sEa[buf][r0 + 8][ks * 8 + q + 4]);
#pragma unroll
            for (int nt = 0; nt < 4; nt++)
                mma_tf32_16n8k8(acc[nt], a0, a1, a2, a3, bfr[nt][ks][0], bfr[nt][ks][1]);
        }

#pragma unroll
        for (int nt = 0; nt < 2; nt++) {
#pragma unroll
            for (int half = 0; half < 2; half++) {
                int row = r0 + half * 8;
                int sN = sIdx[buf][row], dN = sIdx[buf][16 + row];
                int j = w * 16 + nt * 8 + 2 * q;
                const float* pd = Pall + (size_t)dN * 512;
                const float* ps = Pall + (size_t)sN * 512;
                float2 fd  = *(const float2*)(pd + j);
                float2 sd  = *(const float2*)(pd + 128 + j);
                float2 fs2 = *(const float2*)(ps + 256 + j);
                float2 ss2 = *(const float2*)(ps + 384 + j);
                float fa = acc[nt][half * 2 + 0] + fd.x + fs2.x;
                float fb = acc[nt][half * 2 + 1] + fd.y + fs2.y;
                float sa = acc[nt + 2][half * 2 + 0] + sd.x + ss2.x;
                float sb = acc[nt + 2][half * 2 + 1] + sd.y + ss2.y;
                float2 m = make_float2(sigm(fa) * softp(sa), sigm(fb) * softp(sb));
                red2(hout + (size_t)dN * 128 + j, m);
            }
        }
        buf ^= 1;
    }
}

// ---------------- small utility kernels ----------------
__global__ void copy_kernel(const float* __restrict__ a, float* __restrict__ b, int n4) {
    int i = blockIdx.x * blockDim.x + threadIdx.x;
    if (i < n4) ((float4*)b)[i] = ((const float4*)a)[i];
}
__global__ void zero_kernel(float* __restrict__ p, int n) {
    int i = blockIdx.x * blockDim.x + threadIdx.x;
    if (i < n) p[i] = 0.f;
}
__global__ void pool_kernel(const float* __restrict__ h, const int* __restrict__ batch,
                            float* __restrict__ g) {
    int idx = blockIdx.x * blockDim.x + threadIdx.x;
    if (idx >= NN * 32) return;
    int node = idx >> 5, qq = idx & 31;
    float4 v = ((const float4*)h)[idx];
    red4(g + (size_t)batch[node] * 128 + qq * 4, v);
}
__global__ void out_kernel(const float* __restrict__ gf, const float* __restrict__ oW,
                           const float* __restrict__ ob, float* __restrict__ out) {
    int gidx = blockIdx.x * 8 + (threadIdx.x >> 5);
    int lane = threadIdx.x & 31;
    if (gidx >= NG) return;
    float s = 0.f;
#pragma unroll
    for (int k = lane; k < 128; k += 32) s += gf[gidx * 128 + k] * oW[k];
#pragma unroll
    for (int o = 16; o; o >>= 1) s += __shfl_down_sync(0xffffffffu, s, o);
    if (lane == 0) out[gidx] = s + ob[0];
}

// ---------------- launch ----------------
extern "C" void kernel_launch(void* const* d_in, const int* in_sizes, int n_in,
                              void* d_out, int out_size) {
    (void)in_sizes; (void)n_in; (void)out_size;
    const float* x   = (const float*)d_in[0];
    const int*   ei  = (const int*)d_in[1];
    const float* ea  = (const float*)d_in[2];
    const int*   bat = (const int*)d_in[3];
    const float* Wf  = (const float*)d_in[4];
    const float* bf  = (const float*)d_in[5];
    const float* Ws  = (const float*)d_in[6];
    const float* bs  = (const float*)d_in[7];
    const float* m1W0 = (const float*)d_in[8],  *m1b0 = (const float*)d_in[9];
    const float* m1W1 = (const float*)d_in[10], *m1b1 = (const float*)d_in[11];
    const float* m1Wp = (const float*)d_in[12], *m1bp = (const float*)d_in[13];
    const float* m2W0 = (const float*)d_in[14], *m2b0 = (const float*)d_in[15];
    const float* m2W1 = (const float*)d_in[16], *m2b1 = (const float*)d_in[17];
    const float* m2Wp = (const float*)d_in[18], *m2bp = (const float*)d_in[19];
    const float* oW   = (const float*)d_in[20], *ob   = (const float*)d_in[21];
    float* out = (float*)d_out;

    float *pH0, *pH1, *pP, *pW, *pB, *pPool, *pT0g, *pT1g, *pGf;
    cudaGetSymbolAddress((void**)&pH0,  g_h0);
    cudaGetSymbolAddress((void**)&pH1,  g_h1);
    cudaGetSymbolAddress((void**)&pP,   g_P);
    cudaGetSymbolAddress((void**)&pW,   g_Wcat);
    cudaGetSymbolAddress((void**)&pB,   g_bcat);
    cudaGetSymbolAddress((void**)&pPool, g_pool);
    cudaGetSymbolAddress((void**)&pT0g, g_t0g);
    cudaGetSymbolAddress((void**)&pT1g, g_t1g);
    cudaGetSymbolAddress((void**)&pGf,  g_gfin);

    cudaFuncSetAttribute(hmma_gemm, cudaFuncAttributeMaxDynamicSharedMemorySize, HMMA_SMEM);

    const int MB = (NN + 127) / 128;   // 391
    const int EGRID = 304;             // 2 per SM on 152 SMs

    // --- CGConv layer 0 ---
    pack_wcat<<<(512 * 128 + 255) / 256, 256>>>(Wf, Ws, bf, bs, pW, pB, 0);
    hmma_gemm<<<dim3(4, MB), 256, HMMA_SMEM>>>(x, pW, pB, nullptr, pP, NN, 512, 128, 0);
    copy_kernel<<<(NN * 32 + 255) / 256, 256>>>(x, pH0, NN * 32);
    edge_hmma_kernel<<<EGRID, 256>>>(pP, ei, ea, Wf, Ws, 0, pH0);

    // --- CGConv layer 1 ---
    pack_wcat<<<(512 * 128 + 255) / 256, 256>>>(Wf, Ws, bf, bs, pW, pB, 1);
    hmma_gemm<<<dim3(4, MB), 256, HMMA_SMEM>>>(pH0, pW, pB, nullptr, pP, NN, 512, 128, 0);
    copy_kernel<<<(NN * 32 + 255) / 256, 256>>>(pH0, pH1, NN * 32);
    edge_hmma_kernel<<<EGRID, 256>>>(pP, ei, ea, Wf, Ws, 1, pH1);

    // --- node MLP (residual) ---
    float* t0 = pP;
    float* t1 = pP + (size_t)NN * 256;
    hmma_gemm<<<dim3(2, MB), 256, HMMA_SMEM>>>(pH1, m1W0, m1b0, nullptr, t0, NN, 256, 128, 1);
    hmma_gemm<<<dim3(2, MB), 256, HMMA_SMEM>>>(t0, m1W1, m1b1, nullptr, t1, NN, 256, 256, 1);
    hmma_gemm<<<dim3(1, MB), 256, HMMA_SMEM>>>(t1, m1Wp, m1bp, pH1, pH0, NN, 128, 256, 0);

    // --- global add pool ---
    zero_kernel<<<(NG * 128 + 255) / 256, 256>>>(pPool, NG * 128);
    pool_kernel<<<(NN * 32 + 255) / 256, 256>>>(pH0, bat, pPool);

    // --- graph MLP (residual) + head ---
    sgemm_bt<<<dim3(2, 4), 256>>>(pPool, m2W0, m2b0, nullptr, pT0g, NG, 256, 128, 1);
    sgemm_bt<<<dim3(2, 4), 256>>>(pT0g, m2W1, m2b1, nullptr, pT1g, NG, 256, 256, 1);
    sgemm_bt<<<dim3(1, 4), 256>>>(pT1g, m2Wp, m2bp, pPool, pGf, NG, 128, 256, 0);
    out_kernel<<<64, 256>>>(pGf, oW, ob, out);
}